// round 3
// baseline (speedup 1.0000x reference)
#include <cuda_runtime.h>
#include <cuda_bf16.h>
#include <math.h>

#define N_NODES   100000
#define NE        1600000
#define IN_DIM    128
#define HID_DIM   128
#define NCLS      40

// -------- scratch (device globals; no runtime allocation allowed) ----------
__device__ __align__(16) float g_deg [N_NODES];
__device__ __align__(16) float g_dinv[N_NODES];
__device__ __align__(16) float g_H1  [(size_t)N_NODES * HID_DIM];   // x@W1
__device__ __align__(16) float g_AGG [(size_t)N_NODES * HID_DIM];   // layer-1 aggregate -> relu'd H2 (in place)
__device__ __align__(16) float g_H3  [(size_t)N_NODES * NCLS];      // H2@W2
__device__ __align__(16) int   g_src [NE];
__device__ __align__(16) int   g_dst [NE];
__device__ __align__(16) float g_w   [NE];
__device__ int g_is32;   // 1 if edge index dtype is int32, 0 if int64

// ---------------------------------------------------------------------------
// init: zero AGG, deg = 1 (self loop), reset dtype flag
__global__ void k_init() {
    size_t gid = (size_t)blockIdx.x * blockDim.x + threadIdx.x;
    size_t tot = (size_t)N_NODES * HID_DIM;
    if (gid < tot) g_AGG[gid] = 0.0f;
    if (gid < N_NODES) g_deg[gid] = 1.0f;
    if (gid == 0) g_is32 = 0;
}

// probe: interpret first NE 8-byte words (covers full buffer if int32,
// exactly row 0 if int64). Any value >= N  =>  data is int32 pairs.
__global__ void k_probe(const unsigned long long* __restrict__ p) {
    int gid = blockIdx.x * blockDim.x + threadIdx.x;
    if (gid < NE && p[gid] >= (unsigned long long)N_NODES)
        g_is32 = 1;
}

// decode edge list into int32 src/dst with clamping (trap-proof)
__global__ void k_decode(const void* __restrict__ e) {
    int gid = blockIdx.x * blockDim.x + threadIdx.x;
    if (gid >= NE) return;
    int s, d;
    if (g_is32) {
        const int* p = (const int*)e;
        s = p[gid]; d = p[NE + gid];
    } else {
        const long long* p = (const long long*)e;
        s = (int)p[gid]; d = (int)p[NE + gid];
    }
    if ((unsigned)s >= N_NODES) s = 0;
    if ((unsigned)d >= N_NODES) d = 0;
    g_src[gid] = s;
    g_dst[gid] = d;
}

// degree accumulation over edge destinations
__global__ void k_deg() {
    int gid = blockIdx.x * blockDim.x + threadIdx.x;
    if (gid < NE) atomicAdd(&g_deg[g_dst[gid]], 1.0f);
}

__global__ void k_dinv() {
    int gid = blockIdx.x * blockDim.x + threadIdx.x;
    if (gid < N_NODES) g_dinv[gid] = rsqrtf(g_deg[gid]);
}

// per-edge normalization weight
__global__ void k_w() {
    int gid = blockIdx.x * blockDim.x + threadIdx.x;
    if (gid < NE) g_w[gid] = g_dinv[g_src[gid]] * g_dinv[g_dst[gid]];
}

// ---------------------------------------------------------------------------
// GEMM1: g_H1[N,128] = X[N,128] @ W1[128,128]
// BM=64, BN=128, BK=16, 256 threads, per-thread 8x4 register tile.
__global__ void k_gemm1(const float* __restrict__ X, const float* __restrict__ W) {
    __shared__ float As[16][64];
    __shared__ float Bs[16][128];

    const int block_row = blockIdx.x * 64;
    const int tid = threadIdx.x;
    const int tx = tid & 31;
    const int ty = tid >> 5;

    float acc[8][4];
    #pragma unroll
    for (int i = 0; i < 8; i++)
        #pragma unroll
        for (int j = 0; j < 4; j++) acc[i][j] = 0.0f;

    for (int k0 = 0; k0 < 128; k0 += 16) {
        {
            int r  = tid >> 2;
            int c4 = (tid & 3) * 4;
            int row = block_row + r;
            float4 v = make_float4(0.f, 0.f, 0.f, 0.f);
            if (row < N_NODES)
                v = *(const float4*)(X + (size_t)row * 128 + k0 + c4);
            As[c4 + 0][r] = v.x; As[c4 + 1][r] = v.y;
            As[c4 + 2][r] = v.z; As[c4 + 3][r] = v.w;
        }
        #pragma unroll
        for (int i = 0; i < 2; i++) {
            int idx = tid + i * 256;
            int r = idx >> 5;
            int c = (idx & 31) * 4;
            *(float4*)&Bs[r][c] = *(const float4*)(W + (size_t)(k0 + r) * 128 + c);
        }
        __syncthreads();

        #pragma unroll
        for (int k = 0; k < 16; k++) {
            float a[8], b[4];
            *(float4*)&a[0] = *(float4*)&As[k][ty * 8];
            *(float4*)&a[4] = *(float4*)&As[k][ty * 8 + 4];
            *(float4*)&b[0] = *(float4*)&Bs[k][tx * 4];
            #pragma unroll
            for (int i = 0; i < 8; i++)
                #pragma unroll
                for (int j = 0; j < 4; j++)
                    acc[i][j] = fmaf(a[i], b[j], acc[i][j]);
        }
        __syncthreads();
    }

    #pragma unroll
    for (int i = 0; i < 8; i++) {
        int row = block_row + ty * 8 + i;
        if (row < N_NODES) {
            float4 v = make_float4(acc[i][0], acc[i][1], acc[i][2], acc[i][3]);
            *(float4*)(g_H1 + (size_t)row * 128 + tx * 4) = v;
        }
    }
}

// ---------------------------------------------------------------------------
// aggregation layer 1: one warp per edge, each lane handles 4 features
__global__ void k_agg1() {
    int warp = (blockIdx.x * blockDim.x + threadIdx.x) >> 5;
    int lane = threadIdx.x & 31;
    if (warp >= NE) return;
    int src = g_src[warp];
    int dst = g_dst[warp];
    float w = g_w[warp];
    float4 v = *(const float4*)(g_H1 + (size_t)src * 128 + lane * 4);
    float* o = g_AGG + (size_t)dst * 128 + lane * 4;
    atomicAdd(o + 0, w * v.x);
    atomicAdd(o + 1, w * v.y);
    atomicAdd(o + 2, w * v.z);
    atomicAdd(o + 3, w * v.w);
}

// epilogue 1: H2 = relu(AGG + H1*dinv^2 + b1), in place into g_AGG
__global__ void k_epi1(const float* __restrict__ b1) {
    size_t gid = (size_t)blockIdx.x * blockDim.x + threadIdx.x;
    if (gid >= (size_t)N_NODES * 128) return;
    int node = (int)(gid >> 7);
    int f    = (int)(gid & 127);
    float di = g_dinv[node];
    float v = g_AGG[gid] + g_H1[gid] * di * di + b1[f];
    g_AGG[gid] = fmaxf(v, 0.0f);
}

// ---------------------------------------------------------------------------
// GEMM2: g_H3[N,40] = H2[N,128] @ W2[128,40]; warp per row, grid-stride
__global__ void k_gemm2(const float* __restrict__ W2) {
    __shared__ float Ws[128 * NCLS];
    __shared__ float xrow[8][128];
    for (int i = threadIdx.x; i < 128 * NCLS; i += blockDim.x)
        Ws[i] = W2[i];
    __syncthreads();

    int warp = threadIdx.x >> 5;
    int lane = threadIdx.x & 31;
    for (int row = blockIdx.x * 8 + warp; row < N_NODES; row += gridDim.x * 8) {
        *(float4*)&xrow[warp][lane * 4] =
            *(const float4*)(g_AGG + (size_t)row * 128 + lane * 4);
        __syncwarp();
        float acc0 = 0.f, acc1 = 0.f;
        #pragma unroll
        for (int k = 0; k < 128; k++) {
            float xv = xrow[warp][k];
            acc0 = fmaf(xv, Ws[k * NCLS + lane], acc0);
            if (lane < NCLS - 32)
                acc1 = fmaf(xv, Ws[k * NCLS + 32 + lane], acc1);
        }
        g_H3[(size_t)row * NCLS + lane] = acc0;
        if (lane < NCLS - 32)
            g_H3[(size_t)row * NCLS + 32 + lane] = acc1;
        __syncwarp();
    }
}

// epilogue 2 (runs BEFORE agg2): out = H3*dinv^2 + b2  (self loop + bias)
__global__ void k_epi2(const float* __restrict__ b2, float* __restrict__ out) {
    size_t gid = (size_t)blockIdx.x * blockDim.x + threadIdx.x;
    if (gid >= (size_t)N_NODES * NCLS) return;
    int node = (int)(gid / NCLS);
    int c    = (int)(gid - (size_t)node * NCLS);
    float di = g_dinv[node];
    out[gid] = g_H3[gid] * di * di + b2[c];
}

// aggregation layer 2: blockDim = 320 (8 edges x 40 classes per block)
__global__ void k_agg2(float* __restrict__ out) {
    int eloc = threadIdx.x / NCLS;
    int c    = threadIdx.x - eloc * NCLS;
    int edge = blockIdx.x * 8 + eloc;
    if (edge >= NE) return;
    int src = g_src[edge];
    int dst = g_dst[edge];
    float w = g_w[edge];
    float v = g_H3[(size_t)src * NCLS + c];
    atomicAdd(&out[(size_t)dst * NCLS + c], w * v);
}

// ---------------------------------------------------------------------------
extern "C" void kernel_launch(void* const* d_in, const int* in_sizes, int n_in,
                              void* d_out, int out_size) {
    const float* x  = (const float*)d_in[0];
    const void*  e  = d_in[1];                  // [2, E], int32 or int64
    const float* W1 = (const float*)d_in[2];
    const float* b1 = (const float*)d_in[3];
    const float* W2 = (const float*)d_in[4];
    const float* b2 = (const float*)d_in[5];
    float* out = (float*)d_out;

    const int EB = (NE + 255) / 256;

    // 1. init (zero AGG, deg=1, flag=0)
    {
        size_t tot = (size_t)N_NODES * HID_DIM;
        k_init<<<(int)((tot + 255) / 256), 256>>>();
    }
    // 2. probe dtype + decode edges
    k_probe<<<EB, 256>>>((const unsigned long long*)e);
    k_decode<<<EB, 256>>>(e);
    // 3. degree, dinv, edge weights
    k_deg<<<EB, 256>>>();
    k_dinv<<<(N_NODES + 255) / 256, 256>>>();
    k_w<<<EB, 256>>>();
    // 4. GEMM1
    k_gemm1<<<(N_NODES + 63) / 64, 256>>>(x, W1);
    // 5. edge aggregation layer 1 (warp per edge)
    {
        long long threads = (long long)NE * 32;
        k_agg1<<<(int)((threads + 255) / 256), 256>>>();
    }
    // 6. epilogue 1 (bias + self loop + relu)
    {
        size_t tot = (size_t)N_NODES * 128;
        k_epi1<<<(int)((tot + 255) / 256), 256>>>(b1);
    }
    // 7. GEMM2
    k_gemm2<<<1184, 256>>>(W2);
    // 8. epilogue 2: initialize output with self-loop + bias
    {
        size_t tot = (size_t)N_NODES * NCLS;
        k_epi2<<<(int)((tot + 255) / 256), 256>>>(b2, out);
    }
    // 9. edge aggregation layer 2
    k_agg2<<<(NE + 7) / 8, 320>>>(out);
}

// round 4
// speedup vs baseline: 2.1645x; 2.1645x over previous
#include <cuda_runtime.h>
#include <cuda_bf16.h>
#include <math.h>

#define N_NODES   100000
#define NE        1600000
#define IN_DIM    128
#define HID_DIM   128
#define NCLS      40

// -------- scratch (device globals; no runtime allocation allowed) ----------
__device__ __align__(16) float g_dinv[N_NODES];
__device__ __align__(16) float g_H1s [(size_t)N_NODES * HID_DIM];  // dinv * (x@W1)
__device__ __align__(16) float g_H2  [(size_t)N_NODES * HID_DIM];  // relu'd layer-1 out
__device__ __align__(16) float g_H3s [(size_t)N_NODES * NCLS];     // dinv * (H2@W2)
__device__ __align__(16) int   g_src [NE];
__device__ __align__(16) int   g_dst [NE];
__device__ __align__(16) int   g_csr [NE];          // src ids grouped by dst
__device__ __align__(16) int   g_cnt [N_NODES];     // in-degree (excl self)
__device__ __align__(16) int   g_cur [N_NODES];     // scatter cursors
__device__ __align__(16) int   g_rowptr[N_NODES + 1];
__device__ int g_is32;

// ---------------------------------------------------------------------------
__global__ void k_init() {
    int gid = blockIdx.x * blockDim.x + threadIdx.x;
    if (gid < N_NODES) { g_cnt[gid] = 0; g_cur[gid] = 0; }
    if (gid == 0) g_is32 = 0;
}

// probe: if edges are really int32 pairs, reading them as u64 gives huge values
__global__ void k_probe(const unsigned long long* __restrict__ p) {
    int gid = blockIdx.x * blockDim.x + threadIdx.x;
    if (gid < NE && p[gid] >= (unsigned long long)N_NODES)
        g_is32 = 1;
}

// decode edges -> int32 (clamped, trap-proof) + count in-degrees
__global__ void k_decode(const void* __restrict__ e) {
    int gid = blockIdx.x * blockDim.x + threadIdx.x;
    if (gid >= NE) return;
    int s, d;
    if (g_is32) {
        const int* p = (const int*)e;
        s = p[gid]; d = p[NE + gid];
    } else {
        const long long* p = (const long long*)e;
        s = (int)p[gid]; d = (int)p[NE + gid];
    }
    if ((unsigned)s >= N_NODES) s = 0;
    if ((unsigned)d >= N_NODES) d = 0;
    g_src[gid] = s;
    g_dst[gid] = d;
    atomicAdd(&g_cnt[d], 1);
}

// single-block exclusive scan of g_cnt -> g_rowptr  (1024 threads)
__global__ void k_scan() {
    __shared__ int part[1024];
    const int t  = threadIdx.x;
    const int CH = (N_NODES + 1023) / 1024;
    int beg = t * CH;
    int end = beg + CH; if (end > N_NODES) end = N_NODES;
    if (beg > N_NODES) beg = N_NODES;
    int s = 0;
    for (int i = beg; i < end; i++) s += g_cnt[i];
    part[t] = s;
    __syncthreads();
    for (int off = 1; off < 1024; off <<= 1) {
        int v = 0;
        if (t >= off) v = part[t - off];
        __syncthreads();
        if (t >= off) part[t] += v;
        __syncthreads();
    }
    int run = (t == 0) ? 0 : part[t - 1];
    for (int i = beg; i < end; i++) { int c = g_cnt[i]; g_rowptr[i] = run; run += c; }
    if (t == 1023) g_rowptr[N_NODES] = run;
}

// scatter src ids into dst buckets
__global__ void k_scatter() {
    int gid = blockIdx.x * blockDim.x + threadIdx.x;
    if (gid >= NE) return;
    int d = g_dst[gid];
    int pos = g_rowptr[d] + atomicAdd(&g_cur[d], 1);
    g_csr[pos] = g_src[gid];
}

// dinv from rowptr diff (+1 self loop)
__global__ void k_dinv() {
    int gid = blockIdx.x * blockDim.x + threadIdx.x;
    if (gid < N_NODES)
        g_dinv[gid] = rsqrtf((float)(g_rowptr[gid + 1] - g_rowptr[gid] + 1));
}

// ---------------------------------------------------------------------------
// GEMM1: g_H1s[N,128] = dinv[row] * (X[N,128] @ W1[128,128])
__global__ void k_gemm1(const float* __restrict__ X, const float* __restrict__ W) {
    __shared__ float As[16][64];
    __shared__ float Bs[16][128];

    const int block_row = blockIdx.x * 64;
    const int tid = threadIdx.x;
    const int tx = tid & 31;
    const int ty = tid >> 5;

    float acc[8][4];
    #pragma unroll
    for (int i = 0; i < 8; i++)
        #pragma unroll
        for (int j = 0; j < 4; j++) acc[i][j] = 0.0f;

    for (int k0 = 0; k0 < 128; k0 += 16) {
        {
            int r  = tid >> 2;
            int c4 = (tid & 3) * 4;
            int row = block_row + r;
            float4 v = make_float4(0.f, 0.f, 0.f, 0.f);
            if (row < N_NODES)
                v = *(const float4*)(X + (size_t)row * 128 + k0 + c4);
            As[c4 + 0][r] = v.x; As[c4 + 1][r] = v.y;
            As[c4 + 2][r] = v.z; As[c4 + 3][r] = v.w;
        }
        #pragma unroll
        for (int i = 0; i < 2; i++) {
            int idx = tid + i * 256;
            int r = idx >> 5;
            int c = (idx & 31) * 4;
            *(float4*)&Bs[r][c] = *(const float4*)(W + (size_t)(k0 + r) * 128 + c);
        }
        __syncthreads();

        #pragma unroll
        for (int k = 0; k < 16; k++) {
            float a[8], b[4];
            *(float4*)&a[0] = *(float4*)&As[k][ty * 8];
            *(float4*)&a[4] = *(float4*)&As[k][ty * 8 + 4];
            *(float4*)&b[0] = *(float4*)&Bs[k][tx * 4];
            #pragma unroll
            for (int i = 0; i < 8; i++)
                #pragma unroll
                for (int j = 0; j < 4; j++)
                    acc[i][j] = fmaf(a[i], b[j], acc[i][j]);
        }
        __syncthreads();
    }

    #pragma unroll
    for (int i = 0; i < 8; i++) {
        int row = block_row + ty * 8 + i;
        if (row < N_NODES) {
            float di = g_dinv[row];
            float4 v = make_float4(acc[i][0] * di, acc[i][1] * di,
                                   acc[i][2] * di, acc[i][3] * di);
            *(float4*)(g_H1s + (size_t)row * 128 + tx * 4) = v;
        }
    }
}

// ---------------------------------------------------------------------------
// Fused aggregation + epilogue layer 1 (gather, no atomics):
// H2[n] = relu( dinv[n] * ( sum_{s in in(n)} H1s[s] + H1s[n] ) + b1 )
// warp per node, lane holds float4 (128 feats / 32 lanes)
__global__ void k_agg1(const float* __restrict__ b1) {
    int node = blockIdx.x * 8 + (threadIdx.x >> 5);
    int lane = threadIdx.x & 31;
    if (node >= N_NODES) return;

    int beg = g_rowptr[node];
    int end = g_rowptr[node + 1];
    const size_t fo = (size_t)lane * 4;

    // self loop
    float4 acc = *(const float4*)(g_H1s + (size_t)node * 128 + fo);

    int j = beg;
    for (; j + 4 <= end; j += 4) {
        int s0 = g_csr[j], s1 = g_csr[j + 1], s2 = g_csr[j + 2], s3 = g_csr[j + 3];
        float4 a0 = *(const float4*)(g_H1s + (size_t)s0 * 128 + fo);
        float4 a1 = *(const float4*)(g_H1s + (size_t)s1 * 128 + fo);
        float4 a2 = *(const float4*)(g_H1s + (size_t)s2 * 128 + fo);
        float4 a3 = *(const float4*)(g_H1s + (size_t)s3 * 128 + fo);
        acc.x += a0.x + a1.x + a2.x + a3.x;
        acc.y += a0.y + a1.y + a2.y + a3.y;
        acc.z += a0.z + a1.z + a2.z + a3.z;
        acc.w += a0.w + a1.w + a2.w + a3.w;
    }
    for (; j < end; j++) {
        int s = g_csr[j];
        float4 a = *(const float4*)(g_H1s + (size_t)s * 128 + fo);
        acc.x += a.x; acc.y += a.y; acc.z += a.z; acc.w += a.w;
    }

    float di = g_dinv[node];
    float4 bb = *(const float4*)(b1 + fo);
    float4 o;
    o.x = fmaxf(fmaf(acc.x, di, bb.x), 0.0f);
    o.y = fmaxf(fmaf(acc.y, di, bb.y), 0.0f);
    o.z = fmaxf(fmaf(acc.z, di, bb.z), 0.0f);
    o.w = fmaxf(fmaf(acc.w, di, bb.w), 0.0f);
    *(float4*)(g_H2 + (size_t)node * 128 + fo) = o;
}

// ---------------------------------------------------------------------------
// GEMM2: g_H3s[N,40] = dinv[row] * (H2[N,128] @ W2[128,40]); warp per row
__global__ void k_gemm2(const float* __restrict__ W2) {
    __shared__ float Ws[128 * NCLS];
    __shared__ float xrow[8][128];
    for (int i = threadIdx.x; i < 128 * NCLS; i += blockDim.x)
        Ws[i] = W2[i];
    __syncthreads();

    int warp = threadIdx.x >> 5;
    int lane = threadIdx.x & 31;
    for (int row = blockIdx.x * 8 + warp; row < N_NODES; row += gridDim.x * 8) {
        *(float4*)&xrow[warp][lane * 4] =
            *(const float4*)(g_H2 + (size_t)row * 128 + lane * 4);
        __syncwarp();
        float acc0 = 0.f, acc1 = 0.f;
        #pragma unroll
        for (int k = 0; k < 128; k++) {
            float xv = xrow[warp][k];
            acc0 = fmaf(xv, Ws[k * NCLS + lane], acc0);
            if (lane < NCLS - 32)
                acc1 = fmaf(xv, Ws[k * NCLS + 32 + lane], acc1);
        }
        float di = g_dinv[row];
        g_H3s[(size_t)row * NCLS + lane] = acc0 * di;
        if (lane < NCLS - 32)
            g_H3s[(size_t)row * NCLS + 32 + lane] = acc1 * di;
        __syncwarp();
    }
}

// ---------------------------------------------------------------------------
// Fused aggregation + epilogue layer 2 (gather):
// out[n] = dinv[n] * ( sum H3s[s] + H3s[n] ) + b2
// warp per node; lane covers feats {lane, lane+32(<40)}
__global__ void k_agg2(const float* __restrict__ b2, float* __restrict__ out) {
    int node = blockIdx.x * 8 + (threadIdx.x >> 5);
    int lane = threadIdx.x & 31;
    if (node >= N_NODES) return;

    int beg = g_rowptr[node];
    int end = g_rowptr[node + 1];
    bool two = (lane < NCLS - 32);

    const float* selfrow = g_H3s + (size_t)node * NCLS;
    float acc0 = selfrow[lane];
    float acc1 = two ? selfrow[32 + lane] : 0.0f;

    int j = beg;
    for (; j + 4 <= end; j += 4) {
        int s0 = g_csr[j], s1 = g_csr[j + 1], s2 = g_csr[j + 2], s3 = g_csr[j + 3];
        const float* r0 = g_H3s + (size_t)s0 * NCLS;
        const float* r1 = g_H3s + (size_t)s1 * NCLS;
        const float* r2 = g_H3s + (size_t)s2 * NCLS;
        const float* r3 = g_H3s + (size_t)s3 * NCLS;
        acc0 += r0[lane] + r1[lane] + r2[lane] + r3[lane];
        if (two) acc1 += r0[32 + lane] + r1[32 + lane] + r2[32 + lane] + r3[32 + lane];
    }
    for (; j < end; j++) {
        const float* r = g_H3s + (size_t)g_csr[j] * NCLS;
        acc0 += r[lane];
        if (two) acc1 += r[32 + lane];
    }

    float di = g_dinv[node];
    out[(size_t)node * NCLS + lane] = fmaf(acc0, di, b2[lane]);
    if (two)
        out[(size_t)node * NCLS + 32 + lane] = fmaf(acc1, di, b2[32 + lane]);
}

// ---------------------------------------------------------------------------
extern "C" void kernel_launch(void* const* d_in, const int* in_sizes, int n_in,
                              void* d_out, int out_size) {
    const float* x  = (const float*)d_in[0];
    const void*  e  = d_in[1];
    const float* W1 = (const float*)d_in[2];
    const float* b1 = (const float*)d_in[3];
    const float* W2 = (const float*)d_in[4];
    const float* b2 = (const float*)d_in[5];
    float* out = (float*)d_out;

    const int EB = (NE + 255) / 256;
    const int NB = (N_NODES + 255) / 256;

    k_init<<<NB, 256>>>();
    k_probe<<<EB, 256>>>((const unsigned long long*)e);
    k_decode<<<EB, 256>>>(e);
    k_scan<<<1, 1024>>>();
    k_scatter<<<EB, 256>>>();
    k_dinv<<<NB, 256>>>();
    k_gemm1<<<(N_NODES + 63) / 64, 256>>>(x, W1);
    k_agg1<<<(N_NODES + 7) / 8, 256>>>(b1);
    k_gemm2<<<1184, 256>>>(W2);
    k_agg2<<<(N_NODES + 7) / 8, 256>>>(b2, out);
}

// round 5
// speedup vs baseline: 2.6775x; 1.2370x over previous
#include <cuda_runtime.h>
#include <cuda_bf16.h>
#include <math.h>

#define N_NODES   100000
#define NE        1600000
#define IN_DIM    128
#define HID_DIM   128
#define NCLS      40

#define SCAN_CHUNK 1024
#define NB_SCAN    ((N_NODES + SCAN_CHUNK - 1) / SCAN_CHUNK)   // 98

// -------- scratch (device globals; no runtime allocation allowed) ----------
__device__ __align__(16) float g_dinv[N_NODES];
__device__ __align__(16) float g_H1s [(size_t)N_NODES * HID_DIM];  // dinv * (x@W1)
__device__ __align__(16) float g_H2  [(size_t)N_NODES * HID_DIM];  // relu'd layer-1 out
__device__ __align__(16) float g_H3s [(size_t)N_NODES * NCLS];     // dinv * (H2@W2)
__device__ __align__(16) int   g_src [NE];
__device__ __align__(16) int   g_dst [NE];
__device__ __align__(16) int   g_csr [NE];          // src ids grouped by dst
__device__ __align__(16) int   g_cnt [N_NODES];     // in-degree (excl self)
__device__ __align__(16) int   g_cur [N_NODES];     // scatter cursors
__device__ __align__(16) int   g_rowptr[N_NODES + 1];
__device__ __align__(16) int   g_bsum[NB_SCAN];     // per-block count sums
__device__ __align__(16) int   g_boff[NB_SCAN];     // exclusive prefix of bsum
__device__ int g_is32;

// ---------------------------------------------------------------------------
__global__ void k_init() {
    int gid = blockIdx.x * blockDim.x + threadIdx.x;
    if (gid < N_NODES) { g_cnt[gid] = 0; g_cur[gid] = 0; }
    if (gid == 0) g_is32 = 0;
}

// probe: if edges are really int32 pairs, reading them as u64 gives huge values
__global__ void k_probe(const unsigned long long* __restrict__ p) {
    int gid = blockIdx.x * blockDim.x + threadIdx.x;
    if (gid < NE && p[gid] >= (unsigned long long)N_NODES)
        g_is32 = 1;
}

// decode edges -> int32 (clamped, trap-proof) + count in-degrees
__global__ void k_decode(const void* __restrict__ e) {
    int gid = blockIdx.x * blockDim.x + threadIdx.x;
    if (gid >= NE) return;
    int s, d;
    if (g_is32) {
        const int* p = (const int*)e;
        s = p[gid]; d = p[NE + gid];
    } else {
        const long long* p = (const long long*)e;
        s = (int)p[gid]; d = (int)p[NE + gid];
    }
    if ((unsigned)s >= N_NODES) s = 0;
    if ((unsigned)d >= N_NODES) d = 0;
    g_src[gid] = s;
    g_dst[gid] = d;
    atomicAdd(&g_cnt[d], 1);
}

// --------- 3-phase grid-wide exclusive scan of g_cnt -> g_rowptr -----------
// phase 1: per-block sums (98 blocks x 1024 threads)
__global__ void k_bsum() {
    __shared__ int sh[SCAN_CHUNK];
    int i = blockIdx.x * SCAN_CHUNK + threadIdx.x;
    sh[threadIdx.x] = (i < N_NODES) ? g_cnt[i] : 0;
    __syncthreads();
    for (int off = SCAN_CHUNK / 2; off > 0; off >>= 1) {
        if (threadIdx.x < off) sh[threadIdx.x] += sh[threadIdx.x + off];
        __syncthreads();
    }
    if (threadIdx.x == 0) g_bsum[blockIdx.x] = sh[0];
}

// phase 2: scan the 98 block sums (one tiny block)
__global__ void k_sumscan() {
    __shared__ int sh[128];
    int t = threadIdx.x;
    sh[t] = (t < NB_SCAN) ? g_bsum[t] : 0;
    __syncthreads();
    #pragma unroll
    for (int off = 1; off < 128; off <<= 1) {
        int v = (t >= off) ? sh[t - off] : 0;
        __syncthreads();
        sh[t] += v;
        __syncthreads();
    }
    if (t < NB_SCAN) g_boff[t] = sh[t] - g_bsum[t];   // exclusive
}

// phase 3: per-block scan + rowptr emit + dinv (fused)
__global__ void k_rowptr() {
    __shared__ int sh[SCAN_CHUNK];
    int t = threadIdx.x;
    int i = blockIdx.x * SCAN_CHUNK + t;
    int c = (i < N_NODES) ? g_cnt[i] : 0;
    sh[t] = c;
    __syncthreads();
    for (int off = 1; off < SCAN_CHUNK; off <<= 1) {
        int v = (t >= off) ? sh[t - off] : 0;
        __syncthreads();
        sh[t] += v;
        __syncthreads();
    }
    if (i < N_NODES) {
        int excl = g_boff[blockIdx.x] + sh[t] - c;
        g_rowptr[i] = excl;
        g_dinv[i] = rsqrtf((float)(c + 1));
        if (i == N_NODES - 1) g_rowptr[N_NODES] = excl + c;
    }
}

// scatter src ids into dst buckets
__global__ void k_scatter() {
    int gid = blockIdx.x * blockDim.x + threadIdx.x;
    if (gid >= NE) return;
    int d = g_dst[gid];
    int pos = g_rowptr[d] + atomicAdd(&g_cur[d], 1);
    g_csr[pos] = g_src[gid];
}

// ---------------------------------------------------------------------------
// GEMM1: g_H1s[N,128] = dinv[row] * (X[N,128] @ W1[128,128])
__global__ void k_gemm1(const float* __restrict__ X, const float* __restrict__ W) {
    __shared__ float As[16][64];
    __shared__ float Bs[16][128];

    const int block_row = blockIdx.x * 64;
    const int tid = threadIdx.x;
    const int tx = tid & 31;
    const int ty = tid >> 5;

    float acc[8][4];
    #pragma unroll
    for (int i = 0; i < 8; i++)
        #pragma unroll
        for (int j = 0; j < 4; j++) acc[i][j] = 0.0f;

    for (int k0 = 0; k0 < 128; k0 += 16) {
        {
            int r  = tid >> 2;
            int c4 = (tid & 3) * 4;
            int row = block_row + r;
            float4 v = make_float4(0.f, 0.f, 0.f, 0.f);
            if (row < N_NODES)
                v = *(const float4*)(X + (size_t)row * 128 + k0 + c4);
            As[c4 + 0][r] = v.x; As[c4 + 1][r] = v.y;
            As[c4 + 2][r] = v.z; As[c4 + 3][r] = v.w;
        }
        #pragma unroll
        for (int i = 0; i < 2; i++) {
            int idx = tid + i * 256;
            int r = idx >> 5;
            int c = (idx & 31) * 4;
            *(float4*)&Bs[r][c] = *(const float4*)(W + (size_t)(k0 + r) * 128 + c);
        }
        __syncthreads();

        #pragma unroll
        for (int k = 0; k < 16; k++) {
            float a[8], b[4];
            *(float4*)&a[0] = *(float4*)&As[k][ty * 8];
            *(float4*)&a[4] = *(float4*)&As[k][ty * 8 + 4];
            *(float4*)&b[0] = *(float4*)&Bs[k][tx * 4];
            #pragma unroll
            for (int i = 0; i < 8; i++)
                #pragma unroll
                for (int j = 0; j < 4; j++)
                    acc[i][j] = fmaf(a[i], b[j], acc[i][j]);
        }
        __syncthreads();
    }

    #pragma unroll
    for (int i = 0; i < 8; i++) {
        int row = block_row + ty * 8 + i;
        if (row < N_NODES) {
            float di = g_dinv[row];
            float4 v = make_float4(acc[i][0] * di, acc[i][1] * di,
                                   acc[i][2] * di, acc[i][3] * di);
            *(float4*)(g_H1s + (size_t)row * 128 + tx * 4) = v;
        }
    }
}

// ---------------------------------------------------------------------------
// Fused aggregation + epilogue layer 1 (gather, no atomics):
// H2[n] = relu( dinv[n] * ( sum_{s in in(n)} H1s[s] + H1s[n] ) + b1 )
// warp per node, lane holds float4 (128 feats / 32 lanes)
__global__ void k_agg1(const float* __restrict__ b1) {
    int node = blockIdx.x * 8 + (threadIdx.x >> 5);
    int lane = threadIdx.x & 31;
    if (node >= N_NODES) return;

    int beg = g_rowptr[node];
    int end = g_rowptr[node + 1];
    const size_t fo = (size_t)lane * 4;

    // self loop
    float4 acc = *(const float4*)(g_H1s + (size_t)node * 128 + fo);

    int j = beg;
    for (; j + 4 <= end; j += 4) {
        int s0 = g_csr[j], s1 = g_csr[j + 1], s2 = g_csr[j + 2], s3 = g_csr[j + 3];
        float4 a0 = *(const float4*)(g_H1s + (size_t)s0 * 128 + fo);
        float4 a1 = *(const float4*)(g_H1s + (size_t)s1 * 128 + fo);
        float4 a2 = *(const float4*)(g_H1s + (size_t)s2 * 128 + fo);
        float4 a3 = *(const float4*)(g_H1s + (size_t)s3 * 128 + fo);
        acc.x += a0.x + a1.x + a2.x + a3.x;
        acc.y += a0.y + a1.y + a2.y + a3.y;
        acc.z += a0.z + a1.z + a2.z + a3.z;
        acc.w += a0.w + a1.w + a2.w + a3.w;
    }
    for (; j < end; j++) {
        int s = g_csr[j];
        float4 a = *(const float4*)(g_H1s + (size_t)s * 128 + fo);
        acc.x += a.x; acc.y += a.y; acc.z += a.z; acc.w += a.w;
    }

    float di = g_dinv[node];
    float4 bb = *(const float4*)(b1 + fo);
    float4 o;
    o.x = fmaxf(fmaf(acc.x, di, bb.x), 0.0f);
    o.y = fmaxf(fmaf(acc.y, di, bb.y), 0.0f);
    o.z = fmaxf(fmaf(acc.z, di, bb.z), 0.0f);
    o.w = fmaxf(fmaf(acc.w, di, bb.w), 0.0f);
    *(float4*)(g_H2 + (size_t)node * 128 + fo) = o;
}

// ---------------------------------------------------------------------------
// GEMM2: g_H3s[N,40] = dinv[row] * (H2[N,128] @ W2[128,40]); warp per row
__global__ void k_gemm2(const float* __restrict__ W2) {
    __shared__ float Ws[128 * NCLS];
    __shared__ float xrow[8][128];
    for (int i = threadIdx.x; i < 128 * NCLS; i += blockDim.x)
        Ws[i] = W2[i];
    __syncthreads();

    int warp = threadIdx.x >> 5;
    int lane = threadIdx.x & 31;
    for (int row = blockIdx.x * 8 + warp; row < N_NODES; row += gridDim.x * 8) {
        *(float4*)&xrow[warp][lane * 4] =
            *(const float4*)(g_H2 + (size_t)row * 128 + lane * 4);
        __syncwarp();
        float acc0 = 0.f, acc1 = 0.f;
        #pragma unroll
        for (int k = 0; k < 128; k++) {
            float xv = xrow[warp][k];
            acc0 = fmaf(xv, Ws[k * NCLS + lane], acc0);
            if (lane < NCLS - 32)
                acc1 = fmaf(xv, Ws[k * NCLS + 32 + lane], acc1);
        }
        float di = g_dinv[row];
        g_H3s[(size_t)row * NCLS + lane] = acc0 * di;
        if (lane < NCLS - 32)
            g_H3s[(size_t)row * NCLS + 32 + lane] = acc1 * di;
        __syncwarp();
    }
}

// ---------------------------------------------------------------------------
// Fused aggregation + epilogue layer 2 (gather):
// out[n] = dinv[n] * ( sum H3s[s] + H3s[n] ) + b2
// warp per node; lane covers feats {lane, lane+32(<40)}
__global__ void k_agg2(const float* __restrict__ b2, float* __restrict__ out) {
    int node = blockIdx.x * 8 + (threadIdx.x >> 5);
    int lane = threadIdx.x & 31;
    if (node >= N_NODES) return;

    int beg = g_rowptr[node];
    int end = g_rowptr[node + 1];
    bool two = (lane < NCLS - 32);

    const float* selfrow = g_H3s + (size_t)node * NCLS;
    float acc0 = selfrow[lane];
    float acc1 = two ? selfrow[32 + lane] : 0.0f;

    int j = beg;
    for (; j + 4 <= end; j += 4) {
        int s0 = g_csr[j], s1 = g_csr[j + 1], s2 = g_csr[j + 2], s3 = g_csr[j + 3];
        const float* r0 = g_H3s + (size_t)s0 * NCLS;
        const float* r1 = g_H3s + (size_t)s1 * NCLS;
        const float* r2 = g_H3s + (size_t)s2 * NCLS;
        const float* r3 = g_H3s + (size_t)s3 * NCLS;
        acc0 += r0[lane] + r1[lane] + r2[lane] + r3[lane];
        if (two) acc1 += r0[32 + lane] + r1[32 + lane] + r2[32 + lane] + r3[32 + lane];
    }
    for (; j < end; j++) {
        const float* r = g_H3s + (size_t)g_csr[j] * NCLS;
        acc0 += r[lane];
        if (two) acc1 += r[32 + lane];
    }

    float di = g_dinv[node];
    out[(size_t)node * NCLS + lane] = fmaf(acc0, di, b2[lane]);
    if (two)
        out[(size_t)node * NCLS + 32 + lane] = fmaf(acc1, di, b2[32 + lane]);
}

// ---------------------------------------------------------------------------
extern "C" void kernel_launch(void* const* d_in, const int* in_sizes, int n_in,
                              void* d_out, int out_size) {
    const float* x  = (const float*)d_in[0];
    const void*  e  = d_in[1];
    const float* W1 = (const float*)d_in[2];
    const float* b1 = (const float*)d_in[3];
    const float* W2 = (const float*)d_in[4];
    const float* b2 = (const float*)d_in[5];
    float* out = (float*)d_out;

    const int EB = (NE + 255) / 256;
    const int NB = (N_NODES + 255) / 256;

    k_init<<<NB, 256>>>();
    k_probe<<<EB, 256>>>((const unsigned long long*)e);
    k_decode<<<EB, 256>>>(e);
    k_bsum<<<NB_SCAN, SCAN_CHUNK>>>();
    k_sumscan<<<1, 128>>>();
    k_rowptr<<<NB_SCAN, SCAN_CHUNK>>>();
    k_scatter<<<EB, 256>>>();
    k_gemm1<<<(N_NODES + 63) / 64, 256>>>(x, W1);
    k_agg1<<<(N_NODES + 7) / 8, 256>>>(b1);
    k_gemm2<<<1184, 256>>>(W2);
    k_agg2<<<(N_NODES + 7) / 8, 256>>>(b2, out);
}

// round 6
// speedup vs baseline: 3.4996x; 1.3070x over previous
#include <cuda_runtime.h>
#include <cuda_bf16.h>
#include <math.h>

#define N_NODES   100000
#define NE        1600000
#define IN_DIM    128
#define HID_DIM   128
#define NCLS      40

#define SCAN_CHUNK 1024
#define NB_SCAN    ((N_NODES + SCAN_CHUNK - 1) / SCAN_CHUNK)   // 98

// -------- scratch (device globals; no runtime allocation allowed) ----------
__device__ __align__(16) float g_dinv[N_NODES];
__device__ __align__(16) float g_H1s [(size_t)N_NODES * HID_DIM];  // dinv * (x@W1)
__device__ __align__(16) float g_H2  [(size_t)N_NODES * HID_DIM];  // relu'd layer-1 out
__device__ __align__(16) float g_H3s [(size_t)N_NODES * NCLS];     // dinv * (H2@W2)
__device__ __align__(16) int   g_csr [NE];          // src ids grouped by dst
__device__ __align__(16) int   g_cnt [N_NODES];     // in-degree (excl self)
__device__ __align__(16) int   g_cur [N_NODES];     // scatter cursors
__device__ __align__(16) int   g_rowptr[N_NODES + 1];
__device__ __align__(16) int   g_bsum[NB_SCAN];
__device__ __align__(16) int   g_boff[NB_SCAN];
__device__ int g_is32;

// ---- packed fp32x2 helpers (Blackwell FFMA2 path) -------------------------
__device__ __forceinline__ unsigned long long pk2(float lo, float hi) {
    unsigned long long r;
    asm("mov.b64 %0, {%1, %2};" : "=l"(r) : "f"(lo), "f"(hi));
    return r;
}
__device__ __forceinline__ void upk2(unsigned long long v, float& lo, float& hi) {
    asm("mov.b64 {%0, %1}, %2;" : "=f"(lo), "=f"(hi) : "l"(v));
}
__device__ __forceinline__ unsigned long long ffma2(unsigned long long a,
                                                    unsigned long long b,
                                                    unsigned long long c) {
    unsigned long long d;
    asm("fma.rn.f32x2 %0, %1, %2, %3;" : "=l"(d) : "l"(a), "l"(b), "l"(c));
    return d;
}

// ---------------------------------------------------------------------------
__global__ void k_init() {
    int gid = blockIdx.x * blockDim.x + threadIdx.x;
    if (gid < N_NODES) { g_cnt[gid] = 0; g_cur[gid] = 0; }
    if (gid == 0) g_is32 = 0;
}

// probe only the first 2048 u64 words: if edges are int32 pairs, a word is
// src | (next<<32) >= N unless the high half is 0 (P ~1e-5 per word).
__global__ void k_probe(const unsigned long long* __restrict__ p) {
    int gid = blockIdx.x * blockDim.x + threadIdx.x;
    if (gid < 2048 && p[gid] >= (unsigned long long)N_NODES)
        g_is32 = 1;
}

// count in-degrees (reads dst row only)
__global__ void k_count(const void* __restrict__ e) {
    int gid = blockIdx.x * blockDim.x + threadIdx.x;
    if (gid >= NE) return;
    int d;
    if (g_is32) d = ((const int*)e)[NE + gid];
    else        d = (int)((const long long*)e)[NE + gid];
    if ((unsigned)d >= N_NODES) d = 0;
    atomicAdd(&g_cnt[d], 1);
}

// --------- 3-phase grid-wide exclusive scan of g_cnt -> g_rowptr -----------
__global__ void k_bsum() {
    __shared__ int sh[SCAN_CHUNK];
    int i = blockIdx.x * SCAN_CHUNK + threadIdx.x;
    sh[threadIdx.x] = (i < N_NODES) ? g_cnt[i] : 0;
    __syncthreads();
    for (int off = SCAN_CHUNK / 2; off > 0; off >>= 1) {
        if (threadIdx.x < off) sh[threadIdx.x] += sh[threadIdx.x + off];
        __syncthreads();
    }
    if (threadIdx.x == 0) g_bsum[blockIdx.x] = sh[0];
}

__global__ void k_sumscan() {
    __shared__ int sh[128];
    int t = threadIdx.x;
    sh[t] = (t < NB_SCAN) ? g_bsum[t] : 0;
    __syncthreads();
    #pragma unroll
    for (int off = 1; off < 128; off <<= 1) {
        int v = (t >= off) ? sh[t - off] : 0;
        __syncthreads();
        sh[t] += v;
        __syncthreads();
    }
    if (t < NB_SCAN) g_boff[t] = sh[t] - g_bsum[t];
}

// per-block scan + rowptr emit + dinv (fused)
__global__ void k_rowptr() {
    __shared__ int sh[SCAN_CHUNK];
    int t = threadIdx.x;
    int i = blockIdx.x * SCAN_CHUNK + t;
    int c = (i < N_NODES) ? g_cnt[i] : 0;
    sh[t] = c;
    __syncthreads();
    for (int off = 1; off < SCAN_CHUNK; off <<= 1) {
        int v = (t >= off) ? sh[t - off] : 0;
        __syncthreads();
        sh[t] += v;
        __syncthreads();
    }
    if (i < N_NODES) {
        int excl = g_boff[blockIdx.x] + sh[t] - c;
        g_rowptr[i] = excl;
        g_dinv[i] = rsqrtf((float)(c + 1));
        if (i == N_NODES - 1) g_rowptr[N_NODES] = excl + c;
    }
}

// scatter src ids into dst buckets (reads e directly)
__global__ void k_scatter(const void* __restrict__ e) {
    int gid = blockIdx.x * blockDim.x + threadIdx.x;
    if (gid >= NE) return;
    int s, d;
    if (g_is32) {
        const int* p = (const int*)e;
        s = p[gid]; d = p[NE + gid];
    } else {
        const long long* p = (const long long*)e;
        s = (int)p[gid]; d = (int)p[NE + gid];
    }
    if ((unsigned)s >= N_NODES) s = 0;
    if ((unsigned)d >= N_NODES) d = 0;
    int pos = g_rowptr[d] + atomicAdd(&g_cur[d], 1);
    g_csr[pos] = s;
}

// ---------------------------------------------------------------------------
// GEMM1: g_H1s[N,128] = dinv[row] * (X[N,128] @ W1[128,128])
// BM=64, BN=128, BK=16, 256 threads, 8x4 per thread, f32x2 packed FMA.
__global__ void k_gemm1(const float* __restrict__ X, const float* __restrict__ W) {
    __shared__ float As[16][64];
    __shared__ float Bs[16][128];

    const int block_row = blockIdx.x * 64;
    const int tid = threadIdx.x;
    const int tx = tid & 31;
    const int ty = tid >> 5;

    unsigned long long acc2[8][2];   // packed pairs (cols 2j,2j+1)
    #pragma unroll
    for (int i = 0; i < 8; i++) { acc2[i][0] = 0ull; acc2[i][1] = 0ull; }

    for (int k0 = 0; k0 < 128; k0 += 16) {
        {
            int r  = tid >> 2;
            int c4 = (tid & 3) * 4;
            int row = block_row + r;
            float4 v = make_float4(0.f, 0.f, 0.f, 0.f);
            if (row < N_NODES)
                v = *(const float4*)(X + (size_t)row * 128 + k0 + c4);
            As[c4 + 0][r] = v.x; As[c4 + 1][r] = v.y;
            As[c4 + 2][r] = v.z; As[c4 + 3][r] = v.w;
        }
        #pragma unroll
        for (int i = 0; i < 2; i++) {
            int idx = tid + i * 256;
            int r = idx >> 5;
            int c = (idx & 31) * 4;
            *(float4*)&Bs[r][c] = *(const float4*)(W + (size_t)(k0 + r) * 128 + c);
        }
        __syncthreads();

        #pragma unroll
        for (int k = 0; k < 16; k++) {
            float a[8];
            *(float4*)&a[0] = *(float4*)&As[k][ty * 8];
            *(float4*)&a[4] = *(float4*)&As[k][ty * 8 + 4];
            float4 bv = *(float4*)&Bs[k][tx * 4];
            unsigned long long b01 = pk2(bv.x, bv.y);
            unsigned long long b23 = pk2(bv.z, bv.w);
            #pragma unroll
            for (int i = 0; i < 8; i++) {
                unsigned long long ad = pk2(a[i], a[i]);
                acc2[i][0] = ffma2(ad, b01, acc2[i][0]);
                acc2[i][1] = ffma2(ad, b23, acc2[i][1]);
            }
        }
        __syncthreads();
    }

    #pragma unroll
    for (int i = 0; i < 8; i++) {
        int row = block_row + ty * 8 + i;
        if (row < N_NODES) {
            float di = g_dinv[row];
            float4 v;
            upk2(acc2[i][0], v.x, v.y);
            upk2(acc2[i][1], v.z, v.w);
            v.x *= di; v.y *= di; v.z *= di; v.w *= di;
            *(float4*)(g_H1s + (size_t)row * 128 + tx * 4) = v;
        }
    }
}

// ---------------------------------------------------------------------------
// Fused aggregation + epilogue layer 1 (gather, no atomics), unroll 8
__global__ void k_agg1(const float* __restrict__ b1) {
    int node = blockIdx.x * 8 + (threadIdx.x >> 5);
    int lane = threadIdx.x & 31;
    if (node >= N_NODES) return;

    int beg = g_rowptr[node];
    int end = g_rowptr[node + 1];
    const size_t fo = (size_t)lane * 4;

    float4 acc = *(const float4*)(g_H1s + (size_t)node * 128 + fo);  // self loop

    int j = beg;
    for (; j + 8 <= end; j += 8) {
        int idx[8];
        #pragma unroll
        for (int u = 0; u < 8; u++) idx[u] = g_csr[j + u];
        float4 a[8];
        #pragma unroll
        for (int u = 0; u < 8; u++)
            a[u] = *(const float4*)(g_H1s + (size_t)idx[u] * 128 + fo);
        #pragma unroll
        for (int u = 0; u < 8; u++) {
            acc.x += a[u].x; acc.y += a[u].y; acc.z += a[u].z; acc.w += a[u].w;
        }
    }
    for (; j + 2 <= end; j += 2) {
        int s0 = g_csr[j], s1 = g_csr[j + 1];
        float4 a0 = *(const float4*)(g_H1s + (size_t)s0 * 128 + fo);
        float4 a1 = *(const float4*)(g_H1s + (size_t)s1 * 128 + fo);
        acc.x += a0.x + a1.x; acc.y += a0.y + a1.y;
        acc.z += a0.z + a1.z; acc.w += a0.w + a1.w;
    }
    if (j < end) {
        float4 a = *(const float4*)(g_H1s + (size_t)g_csr[j] * 128 + fo);
        acc.x += a.x; acc.y += a.y; acc.z += a.z; acc.w += a.w;
    }

    float di = g_dinv[node];
    float4 bb = *(const float4*)(b1 + fo);
    float4 o;
    o.x = fmaxf(fmaf(acc.x, di, bb.x), 0.0f);
    o.y = fmaxf(fmaf(acc.y, di, bb.y), 0.0f);
    o.z = fmaxf(fmaf(acc.z, di, bb.z), 0.0f);
    o.w = fmaxf(fmaf(acc.w, di, bb.w), 0.0f);
    *(float4*)(g_H2 + (size_t)node * 128 + fo) = o;
}

// ---------------------------------------------------------------------------
// GEMM2 tiled: g_H3s[N,40] = dinv * (H2[N,128] @ W2[128,40])
// BM=256, 256 threads, per-thread 8 rows x 5 cols, W2 stationary in shared.
__global__ void k_gemm2(const float* __restrict__ W2) {
    __shared__ float Ws[128][NCLS];   // 20 KB
    __shared__ float Xs[256][17];     // 17 KB (pad 1: conflict-free)

    const int tid  = threadIdx.x;
    const int row0 = blockIdx.x * 256;
    const int tx = tid & 7;     // cols 5tx..5tx+4
    const int ty = tid >> 3;    // rows 8ty..8ty+7

    for (int i = tid; i < 128 * NCLS; i += 256)
        Ws[i / NCLS][i % NCLS] = W2[i];

    float acc[8][5];
    #pragma unroll
    for (int i = 0; i < 8; i++)
        #pragma unroll
        for (int j = 0; j < 5; j++) acc[i][j] = 0.0f;

    for (int k0 = 0; k0 < 128; k0 += 16) {
        __syncthreads();
        // load 256 rows x 16 k  (1024 float4, 4 per thread)
        #pragma unroll
        for (int l = 0; l < 4; l++) {
            int idx = tid + l * 256;
            int r = idx >> 2;
            int c = (idx & 3) * 4;
            int row = row0 + r;
            float4 v = make_float4(0.f, 0.f, 0.f, 0.f);
            if (row < N_NODES)
                v = *(const float4*)(g_H2 + (size_t)row * 128 + k0 + c);
            Xs[r][c + 0] = v.x; Xs[r][c + 1] = v.y;
            Xs[r][c + 2] = v.z; Xs[r][c + 3] = v.w;
        }
        __syncthreads();

        #pragma unroll
        for (int k = 0; k < 16; k++) {
            float a[8], b[5];
            #pragma unroll
            for (int i = 0; i < 8; i++) a[i] = Xs[ty * 8 + i][k];
            #pragma unroll
            for (int j = 0; j < 5; j++) b[j] = Ws[k0 + k][tx * 5 + j];
            #pragma unroll
            for (int i = 0; i < 8; i++)
                #pragma unroll
                for (int j = 0; j < 5; j++)
                    acc[i][j] = fmaf(a[i], b[j], acc[i][j]);
        }
    }

    #pragma unroll
    for (int i = 0; i < 8; i++) {
        int row = row0 + ty * 8 + i;
        if (row < N_NODES) {
            float di = g_dinv[row];
            #pragma unroll
            for (int j = 0; j < 5; j++)
                g_H3s[(size_t)row * NCLS + tx * 5 + j] = acc[i][j] * di;
        }
    }
}

// ---------------------------------------------------------------------------
// Fused aggregation + epilogue layer 2 (gather)
__global__ void k_agg2(const float* __restrict__ b2, float* __restrict__ out) {
    int node = blockIdx.x * 8 + (threadIdx.x >> 5);
    int lane = threadIdx.x & 31;
    if (node >= N_NODES) return;

    int beg = g_rowptr[node];
    int end = g_rowptr[node + 1];
    bool two = (lane < NCLS - 32);

    const float* selfrow = g_H3s + (size_t)node * NCLS;
    float acc0 = selfrow[lane];
    float acc1 = two ? selfrow[32 + lane] : 0.0f;

    int j = beg;
    for (; j + 4 <= end; j += 4) {
        int s0 = g_csr[j], s1 = g_csr[j + 1], s2 = g_csr[j + 2], s3 = g_csr[j + 3];
        const float* r0 = g_H3s + (size_t)s0 * NCLS;
        const float* r1 = g_H3s + (size_t)s1 * NCLS;
        const float* r2 = g_H3s + (size_t)s2 * NCLS;
        const float* r3 = g_H3s + (size_t)s3 * NCLS;
        acc0 += r0[lane] + r1[lane] + r2[lane] + r3[lane];
        if (two) acc1 += r0[32 + lane] + r1[32 + lane] + r2[32 + lane] + r3[32 + lane];
    }
    for (; j < end; j++) {
        const float* r = g_H3s + (size_t)g_csr[j] * NCLS;
        acc0 += r[lane];
        if (two) acc1 += r[32 + lane];
    }

    float di = g_dinv[node];
    out[(size_t)node * NCLS + lane] = fmaf(acc0, di, b2[lane]);
    if (two)
        out[(size_t)node * NCLS + 32 + lane] = fmaf(acc1, di, b2[32 + lane]);
}

// ---------------------------------------------------------------------------
extern "C" void kernel_launch(void* const* d_in, const int* in_sizes, int n_in,
                              void* d_out, int out_size) {
    const float* x  = (const float*)d_in[0];
    const void*  e  = d_in[1];
    const float* W1 = (const float*)d_in[2];
    const float* b1 = (const float*)d_in[3];
    const float* W2 = (const float*)d_in[4];
    const float* b2 = (const float*)d_in[5];
    float* out = (float*)d_out;

    const int EB = (NE + 255) / 256;
    const int NB = (N_NODES + 255) / 256;

    k_init<<<NB, 256>>>();
    k_probe<<<2, 1024>>>((const unsigned long long*)e);
    k_count<<<EB, 256>>>(e);
    k_bsum<<<NB_SCAN, SCAN_CHUNK>>>();
    k_sumscan<<<1, 128>>>();
    k_rowptr<<<NB_SCAN, SCAN_CHUNK>>>();
    k_scatter<<<EB, 256>>>(e);
    k_gemm1<<<(N_NODES + 63) / 64, 256>>>(x, W1);
    k_agg1<<<(N_NODES + 7) / 8, 256>>>(b1);
    k_gemm2<<<(N_NODES + 255) / 256, 256>>>(W2);
    k_agg2<<<(N_NODES + 7) / 8, 256>>>(b2, out);
}

// round 7
// speedup vs baseline: 3.6127x; 1.0323x over previous
#include <cuda_runtime.h>
#include <cuda_bf16.h>
#include <math.h>

#define N_NODES   100000
#define NE        1600000
#define IN_DIM    128
#define HID_DIM   128
#define NCLS      40

#define SCAN_CHUNK 1024
#define NB_SCAN    ((N_NODES + SCAN_CHUNK - 1) / SCAN_CHUNK)   // 98
#define GB1        ((N_NODES + 63) / 64)                       // 1563 gemm1 tiles
#define SCB        ((NE + 1023) / 1024)                        // 1563 scatter chunks

// -------- scratch (device globals; no runtime allocation allowed) ----------
__device__ __align__(16) float g_dinv[N_NODES];
__device__ __align__(16) float g_H1  [(size_t)N_NODES * HID_DIM];  // x@W1 (UNSCALED)
__device__ __align__(16) float g_H2  [(size_t)N_NODES * HID_DIM];  // relu'd layer-1 out
__device__ __align__(16) float g_H3s [(size_t)N_NODES * NCLS];     // dinv * (H2@W2)
__device__ __align__(16) int   g_csr [NE];          // src ids grouped by dst
__device__ __align__(16) int   g_cnt [N_NODES];     // in-degree (excl self)
__device__ __align__(16) int   g_cur [N_NODES];     // scatter cursors
__device__ __align__(16) int   g_rowptr[N_NODES + 1];
__device__ __align__(16) int   g_bsum[NB_SCAN];
__device__ __align__(16) int   g_boff[NB_SCAN];
__device__ int g_is32;

// ---- packed fp32x2 helpers (Blackwell FFMA2 path) -------------------------
__device__ __forceinline__ unsigned long long pk2(float lo, float hi) {
    unsigned long long r;
    asm("mov.b64 %0, {%1, %2};" : "=l"(r) : "f"(lo), "f"(hi));
    return r;
}
__device__ __forceinline__ void upk2(unsigned long long v, float& lo, float& hi) {
    asm("mov.b64 {%0, %1}, %2;" : "=f"(lo), "=f"(hi) : "l"(v));
}
__device__ __forceinline__ unsigned long long ffma2(unsigned long long a,
                                                    unsigned long long b,
                                                    unsigned long long c) {
    unsigned long long d;
    asm("fma.rn.f32x2 %0, %1, %2, %3;" : "=l"(d) : "l"(a), "l"(b), "l"(c));
    return d;
}

// ---------------------------------------------------------------------------
// init (zero cnt/cur) + probe edge dtype, fused
__global__ void k_init_probe(const unsigned long long* __restrict__ p) {
    int gid = blockIdx.x * blockDim.x + threadIdx.x;
    if (gid == 0) g_is32 = 0;
    if (gid < N_NODES) { g_cnt[gid] = 0; g_cur[gid] = 0; }
}
__global__ void k_probe(const unsigned long long* __restrict__ p) {
    int gid = blockIdx.x * blockDim.x + threadIdx.x;
    if (gid < 2048 && p[gid] >= (unsigned long long)N_NODES)
        g_is32 = 1;
}

// count in-degrees (reads dst row only)
__global__ void k_count(const void* __restrict__ e) {
    int gid = blockIdx.x * blockDim.x + threadIdx.x;
    if (gid >= NE) return;
    int d;
    if (g_is32) d = ((const int*)e)[NE + gid];
    else        d = (int)((const long long*)e)[NE + gid];
    if ((unsigned)d >= N_NODES) d = 0;
    atomicAdd(&g_cnt[d], 1);
}

// --------- 3-phase grid-wide exclusive scan of g_cnt -> g_rowptr -----------
__global__ void k_bsum() {
    __shared__ int sh[SCAN_CHUNK];
    int i = blockIdx.x * SCAN_CHUNK + threadIdx.x;
    sh[threadIdx.x] = (i < N_NODES) ? g_cnt[i] : 0;
    __syncthreads();
    for (int off = SCAN_CHUNK / 2; off > 0; off >>= 1) {
        if (threadIdx.x < off) sh[threadIdx.x] += sh[threadIdx.x + off];
        __syncthreads();
    }
    if (threadIdx.x == 0) g_bsum[blockIdx.x] = sh[0];
}

__global__ void k_sumscan() {
    __shared__ int sh[128];
    int t = threadIdx.x;
    sh[t] = (t < NB_SCAN) ? g_bsum[t] : 0;
    __syncthreads();
    #pragma unroll
    for (int off = 1; off < 128; off <<= 1) {
        int v = (t >= off) ? sh[t - off] : 0;
        __syncthreads();
        sh[t] += v;
        __syncthreads();
    }
    if (t < NB_SCAN) g_boff[t] = sh[t] - g_bsum[t];
}

// per-block scan + rowptr emit + dinv (fused)
__global__ void k_rowptr() {
    __shared__ int sh[SCAN_CHUNK];
    int t = threadIdx.x;
    int i = blockIdx.x * SCAN_CHUNK + t;
    int c = (i < N_NODES) ? g_cnt[i] : 0;
    sh[t] = c;
    __syncthreads();
    for (int off = 1; off < SCAN_CHUNK; off <<= 1) {
        int v = (t >= off) ? sh[t - off] : 0;
        __syncthreads();
        sh[t] += v;
        __syncthreads();
    }
    if (i < N_NODES) {
        int excl = g_boff[blockIdx.x] + sh[t] - c;
        g_rowptr[i] = excl;
        g_dinv[i] = rsqrtf((float)(c + 1));
        if (i == N_NODES - 1) g_rowptr[N_NODES] = excl + c;
    }
}

// ---------------------------------------------------------------------------
// FUSED: GEMM1 (unscaled) + CSR scatter in one launch.
// even blocks: gemm1 tile (blockIdx>>1); odd blocks: 1024-edge scatter chunk.
// GEMM1: g_H1[N,128] = X[N,128] @ W1[128,128]  (BM=64, f32x2 FMA)
__global__ void k_gemm1_scatter(const float* __restrict__ X,
                                const float* __restrict__ W,
                                const void* __restrict__ e) {
    __shared__ float As[16][64];
    __shared__ float Bs[16][128];

    const int tid = threadIdx.x;

    if (blockIdx.x & 1) {
        // ---------------- scatter role ----------------
        int chunk = blockIdx.x >> 1;
        if (chunk < SCB) {
            int base = chunk * 1024 + tid * 4;
            #pragma unroll
            for (int u = 0; u < 4; u++) {
                int gid = base + u;
                if (gid < NE) {
                    int s, d;
                    if (g_is32) {
                        const int* p = (const int*)e;
                        s = p[gid]; d = p[NE + gid];
                    } else {
                        const long long* p = (const long long*)e;
                        s = (int)p[gid]; d = (int)p[NE + gid];
                    }
                    if ((unsigned)s >= N_NODES) s = 0;
                    if ((unsigned)d >= N_NODES) d = 0;
                    int pos = g_rowptr[d] + atomicAdd(&g_cur[d], 1);
                    g_csr[pos] = s;
                }
            }
        }
        return;
    }

    // ---------------- gemm1 role ----------------
    const int block_row = (blockIdx.x >> 1) * 64;
    if (block_row >= N_NODES) return;
    const int tx = tid & 31;
    const int ty = tid >> 5;

    unsigned long long acc2[8][2];
    #pragma unroll
    for (int i = 0; i < 8; i++) { acc2[i][0] = 0ull; acc2[i][1] = 0ull; }

    for (int k0 = 0; k0 < 128; k0 += 16) {
        {
            int r  = tid >> 2;
            int c4 = (tid & 3) * 4;
            int row = block_row + r;
            float4 v = make_float4(0.f, 0.f, 0.f, 0.f);
            if (row < N_NODES)
                v = *(const float4*)(X + (size_t)row * 128 + k0 + c4);
            As[c4 + 0][r] = v.x; As[c4 + 1][r] = v.y;
            As[c4 + 2][r] = v.z; As[c4 + 3][r] = v.w;
        }
        #pragma unroll
        for (int i = 0; i < 2; i++) {
            int idx = tid + i * 256;
            int r = idx >> 5;
            int c = (idx & 31) * 4;
            *(float4*)&Bs[r][c] = *(const float4*)(W + (size_t)(k0 + r) * 128 + c);
        }
        __syncthreads();

        #pragma unroll
        for (int k = 0; k < 16; k++) {
            float a[8];
            *(float4*)&a[0] = *(float4*)&As[k][ty * 8];
            *(float4*)&a[4] = *(float4*)&As[k][ty * 8 + 4];
            float4 bv = *(float4*)&Bs[k][tx * 4];
            unsigned long long b01 = pk2(bv.x, bv.y);
            unsigned long long b23 = pk2(bv.z, bv.w);
            #pragma unroll
            for (int i = 0; i < 8; i++) {
                unsigned long long ad = pk2(a[i], a[i]);
                acc2[i][0] = ffma2(ad, b01, acc2[i][0]);
                acc2[i][1] = ffma2(ad, b23, acc2[i][1]);
            }
        }
        __syncthreads();
    }

    #pragma unroll
    for (int i = 0; i < 8; i++) {
        int row = block_row + ty * 8 + i;
        if (row < N_NODES) {
            float4 v;
            upk2(acc2[i][0], v.x, v.y);
            upk2(acc2[i][1], v.z, v.w);
            *(float4*)(g_H1 + (size_t)row * 128 + tx * 4) = v;
        }
    }
}

// ---------------------------------------------------------------------------
// Fused aggregation + epilogue layer 1 (gather, no atomics), unroll 8.
// H1 is unscaled; apply dinv[src] per gathered row, dinv[node] at the end.
// H2[n] = relu( dinv[n]*( sum_s dinv[s]*H1[s] + dinv[n]*H1[n] ) + b1 )
__global__ void k_agg1(const float* __restrict__ b1) {
    int node = blockIdx.x * 8 + (threadIdx.x >> 5);
    int lane = threadIdx.x & 31;
    if (node >= N_NODES) return;

    int beg = g_rowptr[node];
    int end = g_rowptr[node + 1];
    const size_t fo = (size_t)lane * 4;

    float di = g_dinv[node];
    float4 self = *(const float4*)(g_H1 + (size_t)node * 128 + fo);
    float4 acc;
    acc.x = self.x * di; acc.y = self.y * di;
    acc.z = self.z * di; acc.w = self.w * di;

    int j = beg;
    for (; j + 8 <= end; j += 8) {
        int idx[8];
        #pragma unroll
        for (int u = 0; u < 8; u++) idx[u] = g_csr[j + u];
        float w[8];
        #pragma unroll
        for (int u = 0; u < 8; u++) w[u] = g_dinv[idx[u]];
        float4 a[8];
        #pragma unroll
        for (int u = 0; u < 8; u++)
            a[u] = *(const float4*)(g_H1 + (size_t)idx[u] * 128 + fo);
        #pragma unroll
        for (int u = 0; u < 8; u++) {
            acc.x = fmaf(w[u], a[u].x, acc.x);
            acc.y = fmaf(w[u], a[u].y, acc.y);
            acc.z = fmaf(w[u], a[u].z, acc.z);
            acc.w = fmaf(w[u], a[u].w, acc.w);
        }
    }
    for (; j < end; j++) {
        int s = g_csr[j];
        float w = g_dinv[s];
        float4 a = *(const float4*)(g_H1 + (size_t)s * 128 + fo);
        acc.x = fmaf(w, a.x, acc.x);
        acc.y = fmaf(w, a.y, acc.y);
        acc.z = fmaf(w, a.z, acc.z);
        acc.w = fmaf(w, a.w, acc.w);
    }

    float4 bb = *(const float4*)(b1 + fo);
    float4 o;
    o.x = fmaxf(fmaf(acc.x, di, bb.x), 0.0f);
    o.y = fmaxf(fmaf(acc.y, di, bb.y), 0.0f);
    o.z = fmaxf(fmaf(acc.z, di, bb.z), 0.0f);
    o.w = fmaxf(fmaf(acc.w, di, bb.w), 0.0f);
    *(float4*)(g_H2 + (size_t)node * 128 + fo) = o;
}

// ---------------------------------------------------------------------------
// GEMM2 tiled: g_H3s[N,40] = dinv * (H2[N,128] @ W2[128,40])
__global__ void k_gemm2(const float* __restrict__ W2) {
    __shared__ float Ws[128][NCLS];
    __shared__ float Xs[256][17];

    const int tid  = threadIdx.x;
    const int row0 = blockIdx.x * 256;
    const int tx = tid & 7;
    const int ty = tid >> 3;

    for (int i = tid; i < 128 * NCLS; i += 256)
        Ws[i / NCLS][i % NCLS] = W2[i];

    float acc[8][5];
    #pragma unroll
    for (int i = 0; i < 8; i++)
        #pragma unroll
        for (int j = 0; j < 5; j++) acc[i][j] = 0.0f;

    for (int k0 = 0; k0 < 128; k0 += 16) {
        __syncthreads();
        #pragma unroll
        for (int l = 0; l < 4; l++) {
            int idx = tid + l * 256;
            int r = idx >> 2;
            int c = (idx & 3) * 4;
            int row = row0 + r;
            float4 v = make_float4(0.f, 0.f, 0.f, 0.f);
            if (row < N_NODES)
                v = *(const float4*)(g_H2 + (size_t)row * 128 + k0 + c);
            Xs[r][c + 0] = v.x; Xs[r][c + 1] = v.y;
            Xs[r][c + 2] = v.z; Xs[r][c + 3] = v.w;
        }
        __syncthreads();

        #pragma unroll
        for (int k = 0; k < 16; k++) {
            float a[8], b[5];
            #pragma unroll
            for (int i = 0; i < 8; i++) a[i] = Xs[ty * 8 + i][k];
            #pragma unroll
            for (int j = 0; j < 5; j++) b[j] = Ws[k0 + k][tx * 5 + j];
            #pragma unroll
            for (int i = 0; i < 8; i++)
                #pragma unroll
                for (int j = 0; j < 5; j++)
                    acc[i][j] = fmaf(a[i], b[j], acc[i][j]);
        }
    }

    #pragma unroll
    for (int i = 0; i < 8; i++) {
        int row = row0 + ty * 8 + i;
        if (row < N_NODES) {
            float di = g_dinv[row];
            #pragma unroll
            for (int j = 0; j < 5; j++)
                g_H3s[(size_t)row * NCLS + tx * 5 + j] = acc[i][j] * di;
        }
    }
}

// ---------------------------------------------------------------------------
// Fused aggregation + epilogue layer 2 (gather)
__global__ void k_agg2(const float* __restrict__ b2, float* __restrict__ out) {
    int node = blockIdx.x * 8 + (threadIdx.x >> 5);
    int lane = threadIdx.x & 31;
    if (node >= N_NODES) return;

    int beg = g_rowptr[node];
    int end = g_rowptr[node + 1];
    bool two = (lane < NCLS - 32);

    const float* selfrow = g_H3s + (size_t)node * NCLS;
    float acc0 = selfrow[lane];
    float acc1 = two ? selfrow[32 + lane] : 0.0f;

    int j = beg;
    for (; j + 4 <= end; j += 4) {
        int s0 = g_csr[j], s1 = g_csr[j + 1], s2 = g_csr[j + 2], s3 = g_csr[j + 3];
        const float* r0 = g_H3s + (size_t)s0 * NCLS;
        const float* r1 = g_H3s + (size_t)s1 * NCLS;
        const float* r2 = g_H3s + (size_t)s2 * NCLS;
        const float* r3 = g_H3s + (size_t)s3 * NCLS;
        acc0 += r0[lane] + r1[lane] + r2[lane] + r3[lane];
        if (two) acc1 += r0[32 + lane] + r1[32 + lane] + r2[32 + lane] + r3[32 + lane];
    }
    for (; j < end; j++) {
        const float* r = g_H3s + (size_t)g_csr[j] * NCLS;
        acc0 += r[lane];
        if (two) acc1 += r[32 + lane];
    }

    float di = g_dinv[node];
    out[(size_t)node * NCLS + lane] = fmaf(acc0, di, b2[lane]);
    if (two)
        out[(size_t)node * NCLS + 32 + lane] = fmaf(acc1, di, b2[32 + lane]);
}

// ---------------------------------------------------------------------------
extern "C" void kernel_launch(void* const* d_in, const int* in_sizes, int n_in,
                              void* d_out, int out_size) {
    const float* x  = (const float*)d_in[0];
    const void*  e  = d_in[1];
    const float* W1 = (const float*)d_in[2];
    const float* b1 = (const float*)d_in[3];
    const float* W2 = (const float*)d_in[4];
    const float* b2 = (const float*)d_in[5];
    float* out = (float*)d_out;

    const int EB = (NE + 255) / 256;
    const int NB = (N_NODES + 255) / 256;

    k_init_probe<<<NB, 256>>>((const unsigned long long*)e);
    k_probe<<<2, 1024>>>((const unsigned long long*)e);
    k_count<<<EB, 256>>>(e);
    k_bsum<<<NB_SCAN, SCAN_CHUNK>>>();
    k_sumscan<<<1, 128>>>();
    k_rowptr<<<NB_SCAN, SCAN_CHUNK>>>();
    // fused: gemm1 (even blocks) + scatter (odd blocks)
    {
        int nb = 2 * ((GB1 > SCB ? GB1 : SCB));
        k_gemm1_scatter<<<nb, 256>>>(x, W1, e);
    }
    k_agg1<<<(N_NODES + 7) / 8, 256>>>(b1);
    k_gemm2<<<(N_NODES + 255) / 256, 256>>>(W2);
    k_agg2<<<(N_NODES + 7) / 8, 256>>>(b2, out);
}

// round 8
// speedup vs baseline: 3.7266x; 1.0315x over previous
#include <cuda_runtime.h>
#include <cuda_bf16.h>
#include <math.h>

#define N_NODES   100000
#define NE        1600000
#define IN_DIM    128
#define HID_DIM   128
#define NCLS      40

#define SCAN_CHUNK 1024
#define NB_SCAN    ((N_NODES + SCAN_CHUNK - 1) / SCAN_CHUNK)   // 98
#define GB1        ((N_NODES + 63) / 64)                       // 1563 gemm1 tiles
#define T1_TILES   550                                         // gemm1 tiles in F1
#define ECHUNKS    ((NE + 1023) / 1024)                        // 1563 edge chunks

// -------- scratch (device globals; no runtime allocation allowed) ----------
__device__ __align__(16) float g_dinv[N_NODES];
__device__ __align__(16) float g_H1  [(size_t)N_NODES * HID_DIM];  // x@W1 (UNSCALED)
__device__ __align__(16) float g_H2  [(size_t)N_NODES * HID_DIM];  // relu'd layer-1 out
__device__ __align__(16) float g_H3s [(size_t)N_NODES * NCLS];     // dinv * (H2@W2)
__device__ __align__(16) int   g_csr [NE];          // src ids grouped by dst
__device__ __align__(16) int   g_cnt [N_NODES];     // in-degree (excl self)
__device__ __align__(16) int   g_cur [N_NODES];     // scatter cursors
__device__ __align__(16) int   g_rowptr[N_NODES + 1];
__device__ __align__(16) int   g_bsum[NB_SCAN];
__device__ int g_is32;

// ---- packed fp32x2 helpers (Blackwell FFMA2 path) -------------------------
__device__ __forceinline__ unsigned long long pk2(float lo, float hi) {
    unsigned long long r;
    asm("mov.b64 %0, {%1, %2};" : "=l"(r) : "f"(lo), "f"(hi));
    return r;
}
__device__ __forceinline__ void upk2(unsigned long long v, float& lo, float& hi) {
    asm("mov.b64 {%0, %1}, %2;" : "=f"(lo), "=f"(hi) : "l"(v));
}
__device__ __forceinline__ unsigned long long ffma2(unsigned long long a,
                                                    unsigned long long b,
                                                    unsigned long long c) {
    unsigned long long d;
    asm("fma.rn.f32x2 %0, %1, %2, %3;" : "=l"(d) : "l"(a), "l"(b), "l"(c));
    return d;
}

// ---------------------------------------------------------------------------
__global__ void k_init() {
    int gid = blockIdx.x * blockDim.x + threadIdx.x;
    if (gid < N_NODES) { g_cnt[gid] = 0; g_cur[gid] = 0; }
    if (gid == 0) g_is32 = 0;
}

// probe first 2048 u64 words: int32 pairs ⇒ word >= N unless high half == 0
__global__ void k_probe(const unsigned long long* __restrict__ p) {
    int gid = blockIdx.x * blockDim.x + threadIdx.x;
    if (gid < 2048 && p[gid] >= (unsigned long long)N_NODES)
        g_is32 = 1;
}

// ---------------------------------------------------------------------------
// shared gemm1 tile body (BM=64, BN=128, BK=16, f32x2 FMA)
__device__ __forceinline__ void gemm1_tile(const float* __restrict__ X,
                                           const float* __restrict__ W,
                                           int tile) {
    __shared__ float As[16][64];
    __shared__ float Bs[16][128];

    const int block_row = tile * 64;
    const int tid = threadIdx.x;
    const int tx = tid & 31;
    const int ty = tid >> 5;

    unsigned long long acc2[8][2];
    #pragma unroll
    for (int i = 0; i < 8; i++) { acc2[i][0] = 0ull; acc2[i][1] = 0ull; }

    for (int k0 = 0; k0 < 128; k0 += 16) {
        {
            int r  = tid >> 2;
            int c4 = (tid & 3) * 4;
            int row = block_row + r;
            float4 v = make_float4(0.f, 0.f, 0.f, 0.f);
            if (row < N_NODES)
                v = *(const float4*)(X + (size_t)row * 128 + k0 + c4);
            As[c4 + 0][r] = v.x; As[c4 + 1][r] = v.y;
            As[c4 + 2][r] = v.z; As[c4 + 3][r] = v.w;
        }
        #pragma unroll
        for (int i = 0; i < 2; i++) {
            int idx = tid + i * 256;
            int r = idx >> 5;
            int c = (idx & 31) * 4;
            *(float4*)&Bs[r][c] = *(const float4*)(W + (size_t)(k0 + r) * 128 + c);
        }
        __syncthreads();

        #pragma unroll
        for (int k = 0; k < 16; k++) {
            float a[8];
            *(float4*)&a[0] = *(float4*)&As[k][ty * 8];
            *(float4*)&a[4] = *(float4*)&As[k][ty * 8 + 4];
            float4 bv = *(float4*)&Bs[k][tx * 4];
            unsigned long long b01 = pk2(bv.x, bv.y);
            unsigned long long b23 = pk2(bv.z, bv.w);
            #pragma unroll
            for (int i = 0; i < 8; i++) {
                unsigned long long ad = pk2(a[i], a[i]);
                acc2[i][0] = ffma2(ad, b01, acc2[i][0]);
                acc2[i][1] = ffma2(ad, b23, acc2[i][1]);
            }
        }
        __syncthreads();
    }

    #pragma unroll
    for (int i = 0; i < 8; i++) {
        int row = block_row + ty * 8 + i;
        if (row < N_NODES) {
            float4 v;
            upk2(acc2[i][0], v.x, v.y);
            upk2(acc2[i][1], v.z, v.w);
            *(float4*)(g_H1 + (size_t)row * 128 + tx * 4) = v;
        }
    }
}

// F1: gemm1 tiles [0, T1_TILES) + degree count over all edges
__global__ void k_f1(const float* __restrict__ X, const float* __restrict__ W,
                     const void* __restrict__ e) {
    if (blockIdx.x < T1_TILES) {
        gemm1_tile(X, W, blockIdx.x);
        return;
    }
    int chunk = blockIdx.x - T1_TILES;
    int base = chunk * 1024 + threadIdx.x * 4;
    #pragma unroll
    for (int u = 0; u < 4; u++) {
        int gid = base + u;
        if (gid < NE) {
            int d;
            if (g_is32) d = ((const int*)e)[NE + gid];
            else        d = (int)((const long long*)e)[NE + gid];
            if ((unsigned)d >= N_NODES) d = 0;
            atomicAdd(&g_cnt[d], 1);
        }
    }
}

// F2: gemm1 tiles [T1_TILES, GB1) + CSR scatter over all edges
__global__ void k_f2(const float* __restrict__ X, const float* __restrict__ W,
                     const void* __restrict__ e) {
    if (blockIdx.x < GB1 - T1_TILES) {
        gemm1_tile(X, W, T1_TILES + blockIdx.x);
        return;
    }
    int chunk = blockIdx.x - (GB1 - T1_TILES);
    int base = chunk * 1024 + threadIdx.x * 4;
    #pragma unroll
    for (int u = 0; u < 4; u++) {
        int gid = base + u;
        if (gid < NE) {
            int s, d;
            if (g_is32) {
                const int* p = (const int*)e;
                s = p[gid]; d = p[NE + gid];
            } else {
                const long long* p = (const long long*)e;
                s = (int)p[gid]; d = (int)p[NE + gid];
            }
            if ((unsigned)s >= N_NODES) s = 0;
            if ((unsigned)d >= N_NODES) d = 0;
            int pos = g_rowptr[d] + atomicAdd(&g_cur[d], 1);
            g_csr[pos] = s;
        }
    }
}

// --------- scan: per-block sums, then rowptr (with embedded sum-scan) ------
__global__ void k_bsum() {
    __shared__ int sh[SCAN_CHUNK];
    int i = blockIdx.x * SCAN_CHUNK + threadIdx.x;
    sh[threadIdx.x] = (i < N_NODES) ? g_cnt[i] : 0;
    __syncthreads();
    for (int off = SCAN_CHUNK / 2; off > 0; off >>= 1) {
        if (threadIdx.x < off) sh[threadIdx.x] += sh[threadIdx.x + off];
        __syncthreads();
    }
    if (threadIdx.x == 0) g_bsum[blockIdx.x] = sh[0];
}

__global__ void k_rowptr() {
    __shared__ int sh[SCAN_CHUNK];
    __shared__ int bs[128];
    int t = threadIdx.x;

    // every block redundantly scans the 98 block sums (inclusive)
    if (t < 128) bs[t] = (t < NB_SCAN) ? g_bsum[t] : 0;
    __syncthreads();
    #pragma unroll
    for (int off = 1; off < 128; off <<= 1) {
        int v = 0;
        if (t < 128 && t >= off) v = bs[t - off];
        __syncthreads();
        if (t < 128) bs[t] += v;
        __syncthreads();
    }
    int boff = (blockIdx.x == 0) ? 0 : bs[blockIdx.x - 1];

    int i = blockIdx.x * SCAN_CHUNK + t;
    int c = (i < N_NODES) ? g_cnt[i] : 0;
    sh[t] = c;
    __syncthreads();
    for (int off = 1; off < SCAN_CHUNK; off <<= 1) {
        int v = (t >= off) ? sh[t - off] : 0;
        __syncthreads();
        sh[t] += v;
        __syncthreads();
    }
    if (i < N_NODES) {
        int excl = boff + sh[t] - c;
        g_rowptr[i] = excl;
        g_dinv[i] = rsqrtf((float)(c + 1));
        if (i == N_NODES - 1) g_rowptr[N_NODES] = excl + c;
    }
}

// ---------------------------------------------------------------------------
// Fused aggregation + epilogue layer 1 (gather, no atomics), unroll 8.
// H2[n] = relu( dinv[n]*( sum_s dinv[s]*H1[s] + dinv[n]*H1[n] ) + b1 )
__global__ void k_agg1(const float* __restrict__ b1) {
    int node = blockIdx.x * 8 + (threadIdx.x >> 5);
    int lane = threadIdx.x & 31;
    if (node >= N_NODES) return;

    int beg = g_rowptr[node];
    int end = g_rowptr[node + 1];
    const size_t fo = (size_t)lane * 4;

    float di = g_dinv[node];
    float4 self = *(const float4*)(g_H1 + (size_t)node * 128 + fo);
    float4 acc;
    acc.x = self.x * di; acc.y = self.y * di;
    acc.z = self.z * di; acc.w = self.w * di;

    int j = beg;
    for (; j + 8 <= end; j += 8) {
        int idx[8];
        #pragma unroll
        for (int u = 0; u < 8; u++) idx[u] = g_csr[j + u];
        float w[8];
        #pragma unroll
        for (int u = 0; u < 8; u++) w[u] = g_dinv[idx[u]];
        float4 a[8];
        #pragma unroll
        for (int u = 0; u < 8; u++)
            a[u] = *(const float4*)(g_H1 + (size_t)idx[u] * 128 + fo);
        #pragma unroll
        for (int u = 0; u < 8; u++) {
            acc.x = fmaf(w[u], a[u].x, acc.x);
            acc.y = fmaf(w[u], a[u].y, acc.y);
            acc.z = fmaf(w[u], a[u].z, acc.z);
            acc.w = fmaf(w[u], a[u].w, acc.w);
        }
    }
    for (; j < end; j++) {
        int s = g_csr[j];
        float w = g_dinv[s];
        float4 a = *(const float4*)(g_H1 + (size_t)s * 128 + fo);
        acc.x = fmaf(w, a.x, acc.x);
        acc.y = fmaf(w, a.y, acc.y);
        acc.z = fmaf(w, a.z, acc.z);
        acc.w = fmaf(w, a.w, acc.w);
    }

    float4 bb = *(const float4*)(b1 + fo);
    float4 o;
    o.x = fmaxf(fmaf(acc.x, di, bb.x), 0.0f);
    o.y = fmaxf(fmaf(acc.y, di, bb.y), 0.0f);
    o.z = fmaxf(fmaf(acc.z, di, bb.z), 0.0f);
    o.w = fmaxf(fmaf(acc.w, di, bb.w), 0.0f);
    *(float4*)(g_H2 + (size_t)node * 128 + fo) = o;
}

// ---------------------------------------------------------------------------
// GEMM2 tiled: g_H3s[N,40] = dinv * (H2[N,128] @ W2[128,40])
// BM=128, 256 threads, per-thread 4 rows x 5 cols
__global__ void k_gemm2(const float* __restrict__ W2) {
    __shared__ float Ws[128][NCLS];   // 20 KB
    __shared__ float Xs[128][17];     // 8.7 KB

    const int tid  = threadIdx.x;
    const int row0 = blockIdx.x * 128;
    const int tx = tid & 7;    // cols 5tx..5tx+4
    const int ty = tid >> 3;   // rows 4ty..4ty+3

    for (int i = tid; i < 128 * NCLS; i += 256)
        Ws[i / NCLS][i % NCLS] = W2[i];

    float acc[4][5];
    #pragma unroll
    for (int i = 0; i < 4; i++)
        #pragma unroll
        for (int j = 0; j < 5; j++) acc[i][j] = 0.0f;

    for (int k0 = 0; k0 < 128; k0 += 16) {
        __syncthreads();
        // load 128 rows x 16 k  (512 float4, 2 per thread)
        #pragma unroll
        for (int l = 0; l < 2; l++) {
            int idx = tid + l * 256;
            int r = idx >> 2;
            int c = (idx & 3) * 4;
            int row = row0 + r;
            float4 v = make_float4(0.f, 0.f, 0.f, 0.f);
            if (row < N_NODES)
                v = *(const float4*)(g_H2 + (size_t)row * 128 + k0 + c);
            Xs[r][c + 0] = v.x; Xs[r][c + 1] = v.y;
            Xs[r][c + 2] = v.z; Xs[r][c + 3] = v.w;
        }
        __syncthreads();

        #pragma unroll
        for (int k = 0; k < 16; k++) {
            float a[4], b[5];
            #pragma unroll
            for (int i = 0; i < 4; i++) a[i] = Xs[ty * 4 + i][k];
            #pragma unroll
            for (int j = 0; j < 5; j++) b[j] = Ws[k0 + k][tx * 5 + j];
            #pragma unroll
            for (int i = 0; i < 4; i++)
                #pragma unroll
                for (int j = 0; j < 5; j++)
                    acc[i][j] = fmaf(a[i], b[j], acc[i][j]);
        }
    }

    #pragma unroll
    for (int i = 0; i < 4; i++) {
        int row = row0 + ty * 4 + i;
        if (row < N_NODES) {
            float di = g_dinv[row];
            #pragma unroll
            for (int j = 0; j < 5; j++)
                g_H3s[(size_t)row * NCLS + tx * 5 + j] = acc[i][j] * di;
        }
    }
}

// ---------------------------------------------------------------------------
// Fused aggregation + epilogue layer 2 (gather)
__global__ void k_agg2(const float* __restrict__ b2, float* __restrict__ out) {
    int node = blockIdx.x * 8 + (threadIdx.x >> 5);
    int lane = threadIdx.x & 31;
    if (node >= N_NODES) return;

    int beg = g_rowptr[node];
    int end = g_rowptr[node + 1];
    bool two = (lane < NCLS - 32);

    const float* selfrow = g_H3s + (size_t)node * NCLS;
    float acc0 = selfrow[lane];
    float acc1 = two ? selfrow[32 + lane] : 0.0f;

    int j = beg;
    for (; j + 4 <= end; j += 4) {
        int s0 = g_csr[j], s1 = g_csr[j + 1], s2 = g_csr[j + 2], s3 = g_csr[j + 3];
        const float* r0 = g_H3s + (size_t)s0 * NCLS;
        const float* r1 = g_H3s + (size_t)s1 * NCLS;
        const float* r2 = g_H3s + (size_t)s2 * NCLS;
        const float* r3 = g_H3s + (size_t)s3 * NCLS;
        acc0 += r0[lane] + r1[lane] + r2[lane] + r3[lane];
        if (two) acc1 += r0[32 + lane] + r1[32 + lane] + r2[32 + lane] + r3[32 + lane];
    }
    for (; j < end; j++) {
        const float* r = g_H3s + (size_t)g_csr[j] * NCLS;
        acc0 += r[lane];
        if (two) acc1 += r[32 + lane];
    }

    float di = g_dinv[node];
    out[(size_t)node * NCLS + lane] = fmaf(acc0, di, b2[lane]);
    if (two)
        out[(size_t)node * NCLS + 32 + lane] = fmaf(acc1, di, b2[32 + lane]);
}

// ---------------------------------------------------------------------------
extern "C" void kernel_launch(void* const* d_in, const int* in_sizes, int n_in,
                              void* d_out, int out_size) {
    const float* x  = (const float*)d_in[0];
    const void*  e  = d_in[1];
    const float* W1 = (const float*)d_in[2];
    const float* b1 = (const float*)d_in[3];
    const float* W2 = (const float*)d_in[4];
    const float* b2 = (const float*)d_in[5];
    float* out = (float*)d_out;

    const int NB = (N_NODES + 255) / 256;

    k_init<<<NB, 256>>>();
    k_probe<<<2, 1024>>>((const unsigned long long*)e);
    k_f1<<<T1_TILES + ECHUNKS, 256>>>(x, W1, e);              // gemm1 part A + count
    k_bsum<<<NB_SCAN, SCAN_CHUNK>>>();
    k_rowptr<<<NB_SCAN, SCAN_CHUNK>>>();
    k_f2<<<(GB1 - T1_TILES) + ECHUNKS, 256>>>(x, W1, e);      // gemm1 part B + scatter
    k_agg1<<<(N_NODES + 7) / 8, 256>>>(b1);
    k_gemm2<<<(N_NODES + 127) / 128, 256>>>(W2);
    k_agg2<<<(N_NODES + 7) / 8, 256>>>(b2, out);
}

// round 9
// speedup vs baseline: 4.0543x; 1.0879x over previous
#include <cuda_runtime.h>
#include <cuda_bf16.h>
#include <cuda_fp16.h>
#include <math.h>

#define N_NODES   100000
#define NE        1600000
#define IN_DIM    128
#define HID_DIM   128
#define NCLS      40

#define SCAN_CHUNK 1024
#define NB_SCAN    ((N_NODES + SCAN_CHUNK - 1) / SCAN_CHUNK)   // 98
#define GB1        ((N_NODES + 63) / 64)                       // 1563 gemm1 tiles
#define T1_TILES   550                                         // gemm1 tiles in F1
#define ECHUNKS    ((NE + 1023) / 1024)                        // 1563 edge chunks

// -------- scratch (device globals; no runtime allocation allowed) ----------
__device__ __align__(16) float  g_dinv[N_NODES];
__device__ __align__(16) __half g_H1h [(size_t)N_NODES * HID_DIM];  // fp16 x@W1 (UNSCALED)
__device__ __align__(16) float  g_H2  [(size_t)N_NODES * HID_DIM];  // relu'd layer-1 out (fp32)
__device__ __align__(16) __half g_H3h [(size_t)N_NODES * NCLS];     // fp16 dinv*(H2@W2)
__device__ __align__(16) int    g_csr [NE];
__device__ __align__(16) int    g_cnt [N_NODES];
__device__ __align__(16) int    g_cur [N_NODES];
__device__ __align__(16) int    g_rowptr[N_NODES + 1];
__device__ __align__(16) int    g_bsum[NB_SCAN];
__device__ int g_is32;

// ---- packed fp32x2 helpers (Blackwell FFMA2 path) -------------------------
__device__ __forceinline__ unsigned long long pk2(float lo, float hi) {
    unsigned long long r;
    asm("mov.b64 %0, {%1, %2};" : "=l"(r) : "f"(lo), "f"(hi));
    return r;
}
__device__ __forceinline__ void upk2(unsigned long long v, float& lo, float& hi) {
    asm("mov.b64 {%0, %1}, %2;" : "=f"(lo), "=f"(hi) : "l"(v));
}
__device__ __forceinline__ unsigned long long ffma2(unsigned long long a,
                                                    unsigned long long b,
                                                    unsigned long long c) {
    unsigned long long d;
    asm("fma.rn.f32x2 %0, %1, %2, %3;" : "=l"(d) : "l"(a), "l"(b), "l"(c));
    return d;
}

// ---------------------------------------------------------------------------
__global__ void k_init() {
    int gid = blockIdx.x * blockDim.x + threadIdx.x;
    if (gid < N_NODES) { g_cnt[gid] = 0; g_cur[gid] = 0; }
    if (gid == 0) g_is32 = 0;
}

__global__ void k_probe(const unsigned long long* __restrict__ p) {
    int gid = blockIdx.x * blockDim.x + threadIdx.x;
    if (gid < 2048 && p[gid] >= (unsigned long long)N_NODES)
        g_is32 = 1;
}

// ---------------------------------------------------------------------------
// gemm1 tile body (BM=64, BN=128, BK=16, f32x2 FMA), fp16 output
__device__ __forceinline__ void gemm1_tile(const float* __restrict__ X,
                                           const float* __restrict__ W,
                                           int tile) {
    __shared__ float As[16][64];
    __shared__ float Bs[16][128];

    const int block_row = tile * 64;
    const int tid = threadIdx.x;
    const int tx = tid & 31;
    const int ty = tid >> 5;

    unsigned long long acc2[8][2];
    #pragma unroll
    for (int i = 0; i < 8; i++) { acc2[i][0] = 0ull; acc2[i][1] = 0ull; }

    for (int k0 = 0; k0 < 128; k0 += 16) {
        {
            int r  = tid >> 2;
            int c4 = (tid & 3) * 4;
            int row = block_row + r;
            float4 v = make_float4(0.f, 0.f, 0.f, 0.f);
            if (row < N_NODES)
                v = *(const float4*)(X + (size_t)row * 128 + k0 + c4);
            As[c4 + 0][r] = v.x; As[c4 + 1][r] = v.y;
            As[c4 + 2][r] = v.z; As[c4 + 3][r] = v.w;
        }
        #pragma unroll
        for (int i = 0; i < 2; i++) {
            int idx = tid + i * 256;
            int r = idx >> 5;
            int c = (idx & 31) * 4;
            *(float4*)&Bs[r][c] = *(const float4*)(W + (size_t)(k0 + r) * 128 + c);
        }
        __syncthreads();

        #pragma unroll
        for (int k = 0; k < 16; k++) {
            float a[8];
            *(float4*)&a[0] = *(float4*)&As[k][ty * 8];
            *(float4*)&a[4] = *(float4*)&As[k][ty * 8 + 4];
            float4 bv = *(float4*)&Bs[k][tx * 4];
            unsigned long long b01 = pk2(bv.x, bv.y);
            unsigned long long b23 = pk2(bv.z, bv.w);
            #pragma unroll
            for (int i = 0; i < 8; i++) {
                unsigned long long ad = pk2(a[i], a[i]);
                acc2[i][0] = ffma2(ad, b01, acc2[i][0]);
                acc2[i][1] = ffma2(ad, b23, acc2[i][1]);
            }
        }
        __syncthreads();
    }

    #pragma unroll
    for (int i = 0; i < 8; i++) {
        int row = block_row + ty * 8 + i;
        if (row < N_NODES) {
            float4 v;
            upk2(acc2[i][0], v.x, v.y);
            upk2(acc2[i][1], v.z, v.w);
            __half2 h01 = __floats2half2_rn(v.x, v.y);
            __half2 h23 = __floats2half2_rn(v.z, v.w);
            uint2 packed = make_uint2(*(unsigned*)&h01, *(unsigned*)&h23);
            *(uint2*)(g_H1h + (size_t)row * 128 + tx * 4) = packed;
        }
    }
}

// F1: gemm1 tiles [0, T1_TILES) + degree count over all edges
__global__ void k_f1(const float* __restrict__ X, const float* __restrict__ W,
                     const void* __restrict__ e) {
    if (blockIdx.x < T1_TILES) {
        gemm1_tile(X, W, blockIdx.x);
        return;
    }
    int chunk = blockIdx.x - T1_TILES;
    int base = chunk * 1024 + threadIdx.x * 4;
    #pragma unroll
    for (int u = 0; u < 4; u++) {
        int gid = base + u;
        if (gid < NE) {
            int d;
            if (g_is32) d = ((const int*)e)[NE + gid];
            else        d = (int)((const long long*)e)[NE + gid];
            if ((unsigned)d >= N_NODES) d = 0;
            atomicAdd(&g_cnt[d], 1);
        }
    }
}

// F2: gemm1 tiles [T1_TILES, GB1) + CSR scatter over all edges
__global__ void k_f2(const float* __restrict__ X, const float* __restrict__ W,
                     const void* __restrict__ e) {
    if (blockIdx.x < GB1 - T1_TILES) {
        gemm1_tile(X, W, T1_TILES + blockIdx.x);
        return;
    }
    int chunk = blockIdx.x - (GB1 - T1_TILES);
    int base = chunk * 1024 + threadIdx.x * 4;
    #pragma unroll
    for (int u = 0; u < 4; u++) {
        int gid = base + u;
        if (gid < NE) {
            int s, d;
            if (g_is32) {
                const int* p = (const int*)e;
                s = p[gid]; d = p[NE + gid];
            } else {
                const long long* p = (const long long*)e;
                s = (int)p[gid]; d = (int)p[NE + gid];
            }
            if ((unsigned)s >= N_NODES) s = 0;
            if ((unsigned)d >= N_NODES) d = 0;
            int pos = g_rowptr[d] + atomicAdd(&g_cur[d], 1);
            g_csr[pos] = s;
        }
    }
}

// --------- scan: per-block sums, then rowptr (embedded sum-scan) -----------
__global__ void k_bsum() {
    __shared__ int sh[SCAN_CHUNK];
    int i = blockIdx.x * SCAN_CHUNK + threadIdx.x;
    sh[threadIdx.x] = (i < N_NODES) ? g_cnt[i] : 0;
    __syncthreads();
    for (int off = SCAN_CHUNK / 2; off > 0; off >>= 1) {
        if (threadIdx.x < off) sh[threadIdx.x] += sh[threadIdx.x + off];
        __syncthreads();
    }
    if (threadIdx.x == 0) g_bsum[blockIdx.x] = sh[0];
}

__global__ void k_rowptr() {
    __shared__ int sh[SCAN_CHUNK];
    __shared__ int bs[128];
    int t = threadIdx.x;

    if (t < 128) bs[t] = (t < NB_SCAN) ? g_bsum[t] : 0;
    __syncthreads();
    #pragma unroll
    for (int off = 1; off < 128; off <<= 1) {
        int v = 0;
        if (t < 128 && t >= off) v = bs[t - off];
        __syncthreads();
        if (t < 128) bs[t] += v;
        __syncthreads();
    }
    int boff = (blockIdx.x == 0) ? 0 : bs[blockIdx.x - 1];

    int i = blockIdx.x * SCAN_CHUNK + t;
    int c = (i < N_NODES) ? g_cnt[i] : 0;
    sh[t] = c;
    __syncthreads();
    for (int off = 1; off < SCAN_CHUNK; off <<= 1) {
        int v = (t >= off) ? sh[t - off] : 0;
        __syncthreads();
        sh[t] += v;
        __syncthreads();
    }
    if (i < N_NODES) {
        int excl = boff + sh[t] - c;
        g_rowptr[i] = excl;
        g_dinv[i] = rsqrtf((float)(c + 1));
        if (i == N_NODES - 1) g_rowptr[N_NODES] = excl + c;
    }
}

// ---------------------------------------------------------------------------
// Fused aggregation + epilogue layer 1: fp16 gather, fp32 accumulate.
// H2[n] = relu( dinv[n]*( sum_s dinv[s]*H1[s] + dinv[n]*H1[n] ) + b1 )
// warp per node, lane = 4 feats = one uint2 (2x half2) load.
__global__ void k_agg1(const float* __restrict__ b1) {
    int node = blockIdx.x * 8 + (threadIdx.x >> 5);
    int lane = threadIdx.x & 31;
    if (node >= N_NODES) return;

    int beg = g_rowptr[node];
    int end = g_rowptr[node + 1];

    float di = g_dinv[node];
    float4 acc;
    {
        uint2 u = *(const uint2*)(g_H1h + (size_t)node * 128 + lane * 4);
        float2 f01 = __half22float2(*(__half2*)&u.x);
        float2 f23 = __half22float2(*(__half2*)&u.y);
        acc.x = f01.x * di; acc.y = f01.y * di;
        acc.z = f23.x * di; acc.w = f23.y * di;
    }

    int j = beg;
    for (; j + 8 <= end; j += 8) {
        int idx[8];
        #pragma unroll
        for (int u = 0; u < 8; u++) idx[u] = g_csr[j + u];
        float w[8];
        #pragma unroll
        for (int u = 0; u < 8; u++) w[u] = g_dinv[idx[u]];
        uint2 h[8];
        #pragma unroll
        for (int u = 0; u < 8; u++)
            h[u] = *(const uint2*)(g_H1h + (size_t)idx[u] * 128 + lane * 4);
        #pragma unroll
        for (int u = 0; u < 8; u++) {
            float2 f01 = __half22float2(*(__half2*)&h[u].x);
            float2 f23 = __half22float2(*(__half2*)&h[u].y);
            acc.x = fmaf(w[u], f01.x, acc.x);
            acc.y = fmaf(w[u], f01.y, acc.y);
            acc.z = fmaf(w[u], f23.x, acc.z);
            acc.w = fmaf(w[u], f23.y, acc.w);
        }
    }
    for (; j < end; j++) {
        int s = g_csr[j];
        float w = g_dinv[s];
        uint2 u = *(const uint2*)(g_H1h + (size_t)s * 128 + lane * 4);
        float2 f01 = __half22float2(*(__half2*)&u.x);
        float2 f23 = __half22float2(*(__half2*)&u.y);
        acc.x = fmaf(w, f01.x, acc.x);
        acc.y = fmaf(w, f01.y, acc.y);
        acc.z = fmaf(w, f23.x, acc.z);
        acc.w = fmaf(w, f23.y, acc.w);
    }

    float4 bb = *(const float4*)(b1 + (size_t)lane * 4);
    float4 o;
    o.x = fmaxf(fmaf(acc.x, di, bb.x), 0.0f);
    o.y = fmaxf(fmaf(acc.y, di, bb.y), 0.0f);
    o.z = fmaxf(fmaf(acc.z, di, bb.z), 0.0f);
    o.w = fmaxf(fmaf(acc.w, di, bb.w), 0.0f);
    *(float4*)(g_H2 + (size_t)node * 128 + (size_t)lane * 4) = o;
}

// ---------------------------------------------------------------------------
// GEMM2 tiled: g_H3h[N,40] = fp16( dinv * (H2[N,128] @ W2[128,40]) )
__global__ void k_gemm2(const float* __restrict__ W2) {
    __shared__ float Ws[128][NCLS];
    __shared__ float Xs[128][17];

    const int tid  = threadIdx.x;
    const int row0 = blockIdx.x * 128;
    const int tx = tid & 7;
    const int ty = tid >> 3;

    for (int i = tid; i < 128 * NCLS; i += 256)
        Ws[i / NCLS][i % NCLS] = W2[i];

    float acc[4][5];
    #pragma unroll
    for (int i = 0; i < 4; i++)
        #pragma unroll
        for (int j = 0; j < 5; j++) acc[i][j] = 0.0f;

    for (int k0 = 0; k0 < 128; k0 += 16) {
        __syncthreads();
        #pragma unroll
        for (int l = 0; l < 2; l++) {
            int idx = tid + l * 256;
            int r = idx >> 2;
            int c = (idx & 3) * 4;
            int row = row0 + r;
            float4 v = make_float4(0.f, 0.f, 0.f, 0.f);
            if (row < N_NODES)
                v = *(const float4*)(g_H2 + (size_t)row * 128 + k0 + c);
            Xs[r][c + 0] = v.x; Xs[r][c + 1] = v.y;
            Xs[r][c + 2] = v.z; Xs[r][c + 3] = v.w;
        }
        __syncthreads();

        #pragma unroll
        for (int k = 0; k < 16; k++) {
            float a[4], b[5];
            #pragma unroll
            for (int i = 0; i < 4; i++) a[i] = Xs[ty * 4 + i][k];
            #pragma unroll
            for (int j = 0; j < 5; j++) b[j] = Ws[k0 + k][tx * 5 + j];
            #pragma unroll
            for (int i = 0; i < 4; i++)
                #pragma unroll
                for (int j = 0; j < 5; j++)
                    acc[i][j] = fmaf(a[i], b[j], acc[i][j]);
        }
    }

    #pragma unroll
    for (int i = 0; i < 4; i++) {
        int row = row0 + ty * 4 + i;
        if (row < N_NODES) {
            float di = g_dinv[row];
            #pragma unroll
            for (int j = 0; j < 5; j++)
                g_H3h[(size_t)row * NCLS + tx * 5 + j] =
                    __float2half_rn(acc[i][j] * di);
        }
    }
}

// ---------------------------------------------------------------------------
// Fused aggregation + epilogue layer 2: fp16 gather, fp32 accumulate.
// warp per node; lanes 0..19 each handle 2 classes via one half2 load.
__global__ void k_agg2(const float* __restrict__ b2, float* __restrict__ out) {
    int node = blockIdx.x * 8 + (threadIdx.x >> 5);
    int lane = threadIdx.x & 31;
    if (node >= N_NODES || lane >= NCLS / 2) return;

    int beg = g_rowptr[node];
    int end = g_rowptr[node + 1];

    float2 acc;
    {
        __half2 h = *((const __half2*)(g_H3h + (size_t)node * NCLS) + lane);
        acc = __half22float2(h);
    }

    int j = beg;
    for (; j + 4 <= end; j += 4) {
        int s0 = g_csr[j], s1 = g_csr[j + 1], s2 = g_csr[j + 2], s3 = g_csr[j + 3];
        __half2 h0 = *((const __half2*)(g_H3h + (size_t)s0 * NCLS) + lane);
        __half2 h1 = *((const __half2*)(g_H3h + (size_t)s1 * NCLS) + lane);
        __half2 h2 = *((const __half2*)(g_H3h + (size_t)s2 * NCLS) + lane);
        __half2 h3 = *((const __half2*)(g_H3h + (size_t)s3 * NCLS) + lane);
        float2 f0 = __half22float2(h0), f1 = __half22float2(h1);
        float2 f2 = __half22float2(h2), f3 = __half22float2(h3);
        acc.x += f0.x + f1.x + f2.x + f3.x;
        acc.y += f0.y + f1.y + f2.y + f3.y;
    }
    for (; j < end; j++) {
        __half2 h = *((const __half2*)(g_H3h + (size_t)g_csr[j] * NCLS) + lane);
        float2 f = __half22float2(h);
        acc.x += f.x; acc.y += f.y;
    }

    float di = g_dinv[node];
    int c = lane * 2;
    out[(size_t)node * NCLS + c]     = fmaf(acc.x, di, b2[c]);
    out[(size_t)node * NCLS + c + 1] = fmaf(acc.y, di, b2[c + 1]);
}

// ---------------------------------------------------------------------------
extern "C" void kernel_launch(void* const* d_in, const int* in_sizes, int n_in,
                              void* d_out, int out_size) {
    const float* x  = (const float*)d_in[0];
    const void*  e  = d_in[1];
    const float* W1 = (const float*)d_in[2];
    const float* b1 = (const float*)d_in[3];
    const float* W2 = (const float*)d_in[4];
    const float* b2 = (const float*)d_in[5];
    float* out = (float*)d_out;

    const int NB = (N_NODES + 255) / 256;

    k_init<<<NB, 256>>>();
    k_probe<<<2, 1024>>>((const unsigned long long*)e);
    k_f1<<<T1_TILES + ECHUNKS, 256>>>(x, W1, e);              // gemm1 part A + count
    k_bsum<<<NB_SCAN, SCAN_CHUNK>>>();
    k_rowptr<<<NB_SCAN, SCAN_CHUNK>>>();
    k_f2<<<(GB1 - T1_TILES) + ECHUNKS, 256>>>(x, W1, e);      // gemm1 part B + scatter
    k_agg1<<<(N_NODES + 7) / 8, 256>>>(b1);
    k_gemm2<<<(N_NODES + 127) / 128, 256>>>(W2);
    k_agg2<<<(N_NODES + 7) / 8, 256>>>(b2, out);
}

// round 10
// speedup vs baseline: 4.7857x; 1.1804x over previous
#include <cuda_runtime.h>
#include <cuda_bf16.h>
#include <cuda_fp16.h>
#include <math.h>

#define N_NODES   100000
#define NE        1600000
#define IN_DIM    128
#define HID_DIM   128
#define NCLS      40

#define SCAN_CHUNK 1024
#define NB_SCAN    ((N_NODES + SCAN_CHUNK - 1) / SCAN_CHUNK)   // 98
#define GB1        ((N_NODES + 63) / 64)                       // 1563 gemm1 tiles
#define T1_TILES   780                                         // gemm1 tiles in F1
#define ECHUNKS    ((NE + 1023) / 1024)                        // 1563 edge chunks
#define NB_INIT    ((N_NODES + 255) / 256)                     // 391

// -------- scratch (device globals; no runtime allocation allowed) ----------
__device__ __align__(16) float  g_dinv[N_NODES];
__device__ __align__(16) __half g_W1h [IN_DIM * HID_DIM];           // fp16 W1
__device__ __align__(16) __half g_H1h [(size_t)N_NODES * HID_DIM];  // fp16 x@W1 (UNSCALED)
__device__ __align__(16) float  g_H2  [(size_t)N_NODES * HID_DIM];  // relu'd layer-1 out
__device__ __align__(16) __half g_H3h [(size_t)N_NODES * NCLS];     // fp16 dinv*(H2@W2)
__device__ __align__(16) int    g_csr [NE];
__device__ __align__(16) int    g_cnt [N_NODES];
__device__ __align__(16) int    g_cur [N_NODES];
__device__ __align__(16) int    g_rowptr[N_NODES + 1];
__device__ __align__(16) int    g_bsum[NB_SCAN];
__device__ int g_is32;

// ---------------------------------------------------------------------------
__device__ __forceinline__ unsigned smaddr(const void* p) {
    unsigned a;
    asm("{ .reg .u64 t; cvta.to.shared.u64 t, %1; cvt.u32.u64 %0, t; }"
        : "=r"(a) : "l"(p));
    return a;
}

// ---------------------------------------------------------------------------
// init (zero cnt/cur, flag) + W1 fp32->fp16 conversion (8 extra blocks)
__global__ void k_init(const float* __restrict__ W1) {
    int b = blockIdx.x;
    if (b < NB_INIT) {
        int gid = b * 256 + threadIdx.x;
        if (gid < N_NODES) { g_cnt[gid] = 0; g_cur[gid] = 0; }
        if (gid == 0) g_is32 = 0;
    } else {
        int idx = (b - NB_INIT) * 256 + threadIdx.x;   // 0..2047
        int off = idx * 8;
        if (off < IN_DIM * HID_DIM) {
            float4 v0 = *(const float4*)(W1 + off);
            float4 v1 = *(const float4*)(W1 + off + 4);
            __half2 h0 = __floats2half2_rn(v0.x, v0.y);
            __half2 h1 = __floats2half2_rn(v0.z, v0.w);
            __half2 h2 = __floats2half2_rn(v1.x, v1.y);
            __half2 h3 = __floats2half2_rn(v1.z, v1.w);
            uint4 packed = make_uint4(*(unsigned*)&h0, *(unsigned*)&h1,
                                      *(unsigned*)&h2, *(unsigned*)&h3);
            *(uint4*)(g_W1h + off) = packed;
        }
    }
}

__global__ void k_probe(const unsigned long long* __restrict__ p) {
    int gid = blockIdx.x * blockDim.x + threadIdx.x;
    if (gid < 2048 && p[gid] >= (unsigned long long)N_NODES)
        g_is32 = 1;
}

// ---------------------------------------------------------------------------
// HMMA gemm1 tile: 64 rows x 128 cols, fp16 inputs, fp32 accum, fp16 out.
// 8 warps: warp = (mg 0..3) x (ng 0..1); each m16 x n64.
__device__ __forceinline__ void gemm1_tile_mma(const float* __restrict__ X,
                                               int tile) {
    __shared__ __half As[64][72];    // padded: stride 144B, ldmatrix conflict-free
    __shared__ __half Bs[64][136];   // padded: stride 272B

    const int tid  = threadIdx.x;
    const int wid  = tid >> 5;
    const int lane = tid & 31;
    const int mg   = wid >> 1;       // 0..3
    const int ng   = wid & 1;        // 0..1
    const int block_row = tile * 64;

    float acc[8][4];
    #pragma unroll
    for (int i = 0; i < 8; i++)
        #pragma unroll
        for (int j = 0; j < 4; j++) acc[i][j] = 0.0f;

    const int lr  = lane & 7;
    const int sel = lane >> 3;
    const int aro = (sel & 1) * 8;   // row offset within 16
    const int aco = (sel >> 1) * 8;  // col offset within 16

    #pragma unroll
    for (int kc = 0; kc < 2; kc++) {
        const int k0 = kc * 64;

        // A: 64 rows x 64 fp32 -> fp16 smem (1024 float4, 4/thread, coalesced)
        #pragma unroll
        for (int l = 0; l < 4; l++) {
            int idx = l * 256 + tid;
            int r = idx >> 4;
            int c = (idx & 15) * 4;
            int row = block_row + r;
            float4 v = make_float4(0.f, 0.f, 0.f, 0.f);
            if (row < N_NODES)
                v = *(const float4*)(X + (size_t)row * 128 + k0 + c);
            __half2 h0 = __floats2half2_rn(v.x, v.y);
            __half2 h1 = __floats2half2_rn(v.z, v.w);
            uint2 packed = make_uint2(*(unsigned*)&h0, *(unsigned*)&h1);
            *(uint2*)&As[r][c] = packed;
        }
        // B: 64 k-rows x 128 n fp16 from g_W1h (1024 uint4, 4/thread)
        #pragma unroll
        for (int l = 0; l < 4; l++) {
            int idx = l * 256 + tid;
            int r = idx >> 4;
            int c = (idx & 15) * 8;
            *(uint4*)&Bs[r][c] = *(const uint4*)(g_W1h + (size_t)(k0 + r) * 128 + c);
        }
        __syncthreads();

        #pragma unroll
        for (int ks = 0; ks < 4; ks++) {
            unsigned a0, a1, a2, a3;
            {
                unsigned ad = smaddr(&As[mg * 16 + aro + lr][ks * 16 + aco]);
                asm volatile(
                    "ldmatrix.sync.aligned.m8n8.x4.shared.b16 {%0,%1,%2,%3}, [%4];"
                    : "=r"(a0), "=r"(a1), "=r"(a2), "=r"(a3) : "r"(ad));
            }
            #pragma unroll
            for (int nt2 = 0; nt2 < 4; nt2++) {
                unsigned b0, b1, b2, b3;
                unsigned bd = smaddr(&Bs[ks * 16 + aro + lr][ng * 64 + nt2 * 16 + aco]);
                asm volatile(
                    "ldmatrix.sync.aligned.m8n8.x4.trans.shared.b16 {%0,%1,%2,%3}, [%4];"
                    : "=r"(b0), "=r"(b1), "=r"(b2), "=r"(b3) : "r"(bd));
                asm volatile(
                    "mma.sync.aligned.m16n8k16.row.col.f32.f16.f16.f32 "
                    "{%0,%1,%2,%3},{%4,%5,%6,%7},{%8,%9},{%0,%1,%2,%3};"
                    : "+f"(acc[nt2*2][0]), "+f"(acc[nt2*2][1]),
                      "+f"(acc[nt2*2][2]), "+f"(acc[nt2*2][3])
                    : "r"(a0), "r"(a1), "r"(a2), "r"(a3), "r"(b0), "r"(b1));
                asm volatile(
                    "mma.sync.aligned.m16n8k16.row.col.f32.f16.f16.f32 "
                    "{%0,%1,%2,%3},{%4,%5,%6,%7},{%8,%9},{%0,%1,%2,%3};"
                    : "+f"(acc[nt2*2+1][0]), "+f"(acc[nt2*2+1][1]),
                      "+f"(acc[nt2*2+1][2]), "+f"(acc[nt2*2+1][3])
                    : "r"(a0), "r"(a1), "r"(a2), "r"(a3), "r"(b2), "r"(b3));
            }
        }
        __syncthreads();
    }

    // epilogue: d-frag -> fp16 global
    int g  = lane >> 2;
    int tg = lane & 3;
    #pragma unroll
    for (int nt = 0; nt < 8; nt++) {
        int col = ng * 64 + nt * 8 + tg * 2;
        int row = block_row + mg * 16 + g;
        if (row < N_NODES)
            *(__half2*)(g_H1h + (size_t)row * 128 + col) =
                __floats2half2_rn(acc[nt][0], acc[nt][1]);
        if (row + 8 < N_NODES)
            *(__half2*)(g_H1h + (size_t)(row + 8) * 128 + col) =
                __floats2half2_rn(acc[nt][2], acc[nt][3]);
    }
}

// F1: gemm1 tiles [0, T1_TILES) + degree count over all edges
__global__ void k_f1(const float* __restrict__ X, const void* __restrict__ e) {
    if (blockIdx.x < T1_TILES) {
        gemm1_tile_mma(X, blockIdx.x);
        return;
    }
    int chunk = blockIdx.x - T1_TILES;
    int base = chunk * 1024 + threadIdx.x * 4;
    #pragma unroll
    for (int u = 0; u < 4; u++) {
        int gid = base + u;
        if (gid < NE) {
            int d;
            if (g_is32) d = ((const int*)e)[NE + gid];
            else        d = (int)((const long long*)e)[NE + gid];
            if ((unsigned)d >= N_NODES) d = 0;
            atomicAdd(&g_cnt[d], 1);
        }
    }
}

// F2: gemm1 tiles [T1_TILES, GB1) + CSR scatter over all edges
__global__ void k_f2(const float* __restrict__ X, const void* __restrict__ e) {
    if (blockIdx.x < GB1 - T1_TILES) {
        gemm1_tile_mma(X, T1_TILES + blockIdx.x);
        return;
    }
    int chunk = blockIdx.x - (GB1 - T1_TILES);
    int base = chunk * 1024 + threadIdx.x * 4;
    #pragma unroll
    for (int u = 0; u < 4; u++) {
        int gid = base + u;
        if (gid < NE) {
            int s, d;
            if (g_is32) {
                const int* p = (const int*)e;
                s = p[gid]; d = p[NE + gid];
            } else {
                const long long* p = (const long long*)e;
                s = (int)p[gid]; d = (int)p[NE + gid];
            }
            if ((unsigned)s >= N_NODES) s = 0;
            if ((unsigned)d >= N_NODES) d = 0;
            int pos = g_rowptr[d] + atomicAdd(&g_cur[d], 1);
            g_csr[pos] = s;
        }
    }
}

// --------- scan: per-block sums, then rowptr (embedded sum-scan) -----------
__global__ void k_bsum() {
    __shared__ int sh[SCAN_CHUNK];
    int i = blockIdx.x * SCAN_CHUNK + threadIdx.x;
    sh[threadIdx.x] = (i < N_NODES) ? g_cnt[i] : 0;
    __syncthreads();
    for (int off = SCAN_CHUNK / 2; off > 0; off >>= 1) {
        if (threadIdx.x < off) sh[threadIdx.x] += sh[threadIdx.x + off];
        __syncthreads();
    }
    if (threadIdx.x == 0) g_bsum[blockIdx.x] = sh[0];
}

__global__ void k_rowptr() {
    __shared__ int sh[SCAN_CHUNK];
    __shared__ int bs[128];
    int t = threadIdx.x;

    if (t < 128) bs[t] = (t < NB_SCAN) ? g_bsum[t] : 0;
    __syncthreads();
    #pragma unroll
    for (int off = 1; off < 128; off <<= 1) {
        int v = 0;
        if (t < 128 && t >= off) v = bs[t - off];
        __syncthreads();
        if (t < 128) bs[t] += v;
        __syncthreads();
    }
    int boff = (blockIdx.x == 0) ? 0 : bs[blockIdx.x - 1];

    int i = blockIdx.x * SCAN_CHUNK + t;
    int c = (i < N_NODES) ? g_cnt[i] : 0;
    sh[t] = c;
    __syncthreads();
    for (int off = 1; off < SCAN_CHUNK; off <<= 1) {
        int v = (t >= off) ? sh[t - off] : 0;
        __syncthreads();
        sh[t] += v;
        __syncthreads();
    }
    if (i < N_NODES) {
        int excl = boff + sh[t] - c;
        g_rowptr[i] = excl;
        g_dinv[i] = rsqrtf((float)(c + 1));
        if (i == N_NODES - 1) g_rowptr[N_NODES] = excl + c;
    }
}

// ---------------------------------------------------------------------------
// Fused aggregation + epilogue layer 1: fp16 gather, fp32 accumulate.
__global__ void k_agg1(const float* __restrict__ b1) {
    int node = blockIdx.x * 8 + (threadIdx.x >> 5);
    int lane = threadIdx.x & 31;
    if (node >= N_NODES) return;

    int beg = g_rowptr[node];
    int end = g_rowptr[node + 1];

    float di = g_dinv[node];
    float4 acc;
    {
        uint2 u = *(const uint2*)(g_H1h + (size_t)node * 128 + lane * 4);
        float2 f01 = __half22float2(*(__half2*)&u.x);
        float2 f23 = __half22float2(*(__half2*)&u.y);
        acc.x = f01.x * di; acc.y = f01.y * di;
        acc.z = f23.x * di; acc.w = f23.y * di;
    }

    int j = beg;
    for (; j + 8 <= end; j += 8) {
        int idx[8];
        #pragma unroll
        for (int u = 0; u < 8; u++) idx[u] = g_csr[j + u];
        float w[8];
        #pragma unroll
        for (int u = 0; u < 8; u++) w[u] = g_dinv[idx[u]];
        uint2 h[8];
        #pragma unroll
        for (int u = 0; u < 8; u++)
            h[u] = *(const uint2*)(g_H1h + (size_t)idx[u] * 128 + lane * 4);
        #pragma unroll
        for (int u = 0; u < 8; u++) {
            float2 f01 = __half22float2(*(__half2*)&h[u].x);
            float2 f23 = __half22float2(*(__half2*)&h[u].y);
            acc.x = fmaf(w[u], f01.x, acc.x);
            acc.y = fmaf(w[u], f01.y, acc.y);
            acc.z = fmaf(w[u], f23.x, acc.z);
            acc.w = fmaf(w[u], f23.y, acc.w);
        }
    }
    for (; j < end; j++) {
        int s = g_csr[j];
        float w = g_dinv[s];
        uint2 u = *(const uint2*)(g_H1h + (size_t)s * 128 + lane * 4);
        float2 f01 = __half22float2(*(__half2*)&u.x);
        float2 f23 = __half22float2(*(__half2*)&u.y);
        acc.x = fmaf(w, f01.x, acc.x);
        acc.y = fmaf(w, f01.y, acc.y);
        acc.z = fmaf(w, f23.x, acc.z);
        acc.w = fmaf(w, f23.y, acc.w);
    }

    float4 bb = *(const float4*)(b1 + (size_t)lane * 4);
    float4 o;
    o.x = fmaxf(fmaf(acc.x, di, bb.x), 0.0f);
    o.y = fmaxf(fmaf(acc.y, di, bb.y), 0.0f);
    o.z = fmaxf(fmaf(acc.z, di, bb.z), 0.0f);
    o.w = fmaxf(fmaf(acc.w, di, bb.w), 0.0f);
    *(float4*)(g_H2 + (size_t)node * 128 + (size_t)lane * 4) = o;
}

// ---------------------------------------------------------------------------
// GEMM2 tiled: g_H3h[N,40] = fp16( dinv * (H2[N,128] @ W2[128,40]) )
__global__ void k_gemm2(const float* __restrict__ W2) {
    __shared__ float Ws[128][NCLS];
    __shared__ float Xs[128][17];

    const int tid  = threadIdx.x;
    const int row0 = blockIdx.x * 128;
    const int tx = tid & 7;
    const int ty = tid >> 3;

    for (int i = tid; i < 128 * NCLS; i += 256)
        Ws[i / NCLS][i % NCLS] = W2[i];

    float acc[4][5];
    #pragma unroll
    for (int i = 0; i < 4; i++)
        #pragma unroll
        for (int j = 0; j < 5; j++) acc[i][j] = 0.0f;

    for (int k0 = 0; k0 < 128; k0 += 16) {
        __syncthreads();
        #pragma unroll
        for (int l = 0; l < 2; l++) {
            int idx = tid + l * 256;
            int r = idx >> 2;
            int c = (idx & 3) * 4;
            int row = row0 + r;
            float4 v = make_float4(0.f, 0.f, 0.f, 0.f);
            if (row < N_NODES)
                v = *(const float4*)(g_H2 + (size_t)row * 128 + k0 + c);
            Xs[r][c + 0] = v.x; Xs[r][c + 1] = v.y;
            Xs[r][c + 2] = v.z; Xs[r][c + 3] = v.w;
        }
        __syncthreads();

        #pragma unroll
        for (int k = 0; k < 16; k++) {
            float a[4], b[5];
            #pragma unroll
            for (int i = 0; i < 4; i++) a[i] = Xs[ty * 4 + i][k];
            #pragma unroll
            for (int j = 0; j < 5; j++) b[j] = Ws[k0 + k][tx * 5 + j];
            #pragma unroll
            for (int i = 0; i < 4; i++)
                #pragma unroll
                for (int j = 0; j < 5; j++)
                    acc[i][j] = fmaf(a[i], b[j], acc[i][j]);
        }
    }

    #pragma unroll
    for (int i = 0; i < 4; i++) {
        int row = row0 + ty * 4 + i;
        if (row < N_NODES) {
            float di = g_dinv[row];
            #pragma unroll
            for (int j = 0; j < 5; j++)
                g_H3h[(size_t)row * NCLS + tx * 5 + j] =
                    __float2half_rn(acc[i][j] * di);
        }
    }
}

// ---------------------------------------------------------------------------
// Fused aggregation + epilogue layer 2: fp16 gather, fp32 accumulate.
__global__ void k_agg2(const float* __restrict__ b2, float* __restrict__ out) {
    int node = blockIdx.x * 8 + (threadIdx.x >> 5);
    int lane = threadIdx.x & 31;
    if (node >= N_NODES || lane >= NCLS / 2) return;

    int beg = g_rowptr[node];
    int end = g_rowptr[node + 1];

    float2 acc;
    {
        __half2 h = *((const __half2*)(g_H3h + (size_t)node * NCLS) + lane);
        acc = __half22float2(h);
    }

    int j = beg;
    for (; j + 4 <= end; j += 4) {
        int s0 = g_csr[j], s1 = g_csr[j + 1], s2 = g_csr[j + 2], s3 = g_csr[j + 3];
        __half2 h0 = *((const __half2*)(g_H3h + (size_t)s0 * NCLS) + lane);
        __half2 h1 = *((const __half2*)(g_H3h + (size_t)s1 * NCLS) + lane);
        __half2 h2 = *((const __half2*)(g_H3h + (size_t)s2 * NCLS) + lane);
        __half2 h3 = *((const __half2*)(g_H3h + (size_t)s3 * NCLS) + lane);
        float2 f0 = __half22float2(h0), f1 = __half22float2(h1);
        float2 f2 = __half22float2(h2), f3 = __half22float2(h3);
        acc.x += f0.x + f1.x + f2.x + f3.x;
        acc.y += f0.y + f1.y + f2.y + f3.y;
    }
    for (; j < end; j++) {
        __half2 h = *((const __half2*)(g_H3h + (size_t)g_csr[j] * NCLS) + lane);
        float2 f = __half22float2(h);
        acc.x += f.x; acc.y += f.y;
    }

    float di = g_dinv[node];
    int c = lane * 2;
    out[(size_t)node * NCLS + c]     = fmaf(acc.x, di, b2[c]);
    out[(size_t)node * NCLS + c + 1] = fmaf(acc.y, di, b2[c + 1]);
}

// ---------------------------------------------------------------------------
extern "C" void kernel_launch(void* const* d_in, const int* in_sizes, int n_in,
                              void* d_out, int out_size) {
    const float* x  = (const float*)d_in[0];
    const void*  e  = d_in[1];
    const float* W1 = (const float*)d_in[2];
    const float* b1 = (const float*)d_in[3];
    const float* W2 = (const float*)d_in[4];
    const float* b2 = (const float*)d_in[5];
    float* out = (float*)d_out;

    k_init<<<NB_INIT + 8, 256>>>(W1);
    k_probe<<<2, 1024>>>((const unsigned long long*)e);
    k_f1<<<T1_TILES + ECHUNKS, 256>>>(x, e);               // gemm1 part A + count
    k_bsum<<<NB_SCAN, SCAN_CHUNK>>>();
    k_rowptr<<<NB_SCAN, SCAN_CHUNK>>>();
    k_f2<<<(GB1 - T1_TILES) + ECHUNKS, 256>>>(x, e);       // gemm1 part B + scatter
    k_agg1<<<(N_NODES + 7) / 8, 256>>>(b1);
    k_gemm2<<<(N_NODES + 127) / 128, 256>>>(W2);
    k_agg2<<<(N_NODES + 7) / 8, 256>>>(b2, out);
}

// round 11
// speedup vs baseline: 5.9563x; 1.2446x over previous
#include <cuda_runtime.h>
#include <cuda_bf16.h>
#include <cuda_fp16.h>
#include <math.h>

#define N_NODES   100000
#define NE        1600000
#define IN_DIM    128
#define HID_DIM   128
#define NCLS      40

#define SCAN_CHUNK 1024
#define NB_SCAN    ((N_NODES + SCAN_CHUNK - 1) / SCAN_CHUNK)   // 98
#define GB1        ((N_NODES + 63) / 64)                       // 1563 gemm1 tiles
#define T1_TILES   780                                         // gemm1 tiles in F1
#define ECHUNKS    ((NE + 1023) / 1024)                        // 1563 edge chunks
#define NB_INIT    ((N_NODES + 255) / 256)                     // 391

// -------- scratch (device globals; no runtime allocation allowed) ----------
__device__ __align__(16) float  g_dinv[N_NODES];
__device__ __align__(16) __half g_W1h [IN_DIM * HID_DIM];           // fp16 W1
__device__ __align__(16) __half g_W2h [HID_DIM * NCLS];             // fp16 W2
__device__ __align__(16) __half g_H1h [(size_t)N_NODES * HID_DIM];  // fp16 x@W1 (UNSCALED)
__device__ __align__(16) __half g_H2h [(size_t)N_NODES * HID_DIM];  // fp16 relu'd layer-1 out
__device__ __align__(16) __half g_H3h [(size_t)N_NODES * NCLS];     // fp16 dinv*(H2@W2)
__device__ __align__(16) int    g_csr [NE];
__device__ __align__(16) int    g_cnt [N_NODES];
__device__ __align__(16) int    g_cur [N_NODES];
__device__ __align__(16) int    g_rowptr[N_NODES + 1];
__device__ __align__(16) int    g_bsum[NB_SCAN];
__device__ int g_is32;   // sticky: zero-init at load; input-deterministic

// ---------------------------------------------------------------------------
__device__ __forceinline__ unsigned smaddr(const void* p) {
    unsigned a;
    asm("{ .reg .u64 t; cvta.to.shared.u64 t, %1; cvt.u32.u64 %0, t; }"
        : "=r"(a) : "l"(p));
    return a;
}

// ---------------------------------------------------------------------------
// init: zero cnt/cur + W1/W2 fp16 conversion + dtype probe, one launch
__global__ void k_init(const float* __restrict__ W1, const float* __restrict__ W2,
                       const unsigned long long* __restrict__ ep) {
    int b = blockIdx.x;
    if (b < NB_INIT) {
        int gid = b * 256 + threadIdx.x;
        if (gid < N_NODES) { g_cnt[gid] = 0; g_cur[gid] = 0; }
    } else if (b < NB_INIT + 8) {
        int idx = (b - NB_INIT) * 256 + threadIdx.x;   // 0..2047
        int off = idx * 8;
        if (off < IN_DIM * HID_DIM) {
            float4 v0 = *(const float4*)(W1 + off);
            float4 v1 = *(const float4*)(W1 + off + 4);
            __half2 h0 = __floats2half2_rn(v0.x, v0.y);
            __half2 h1 = __floats2half2_rn(v0.z, v0.w);
            __half2 h2 = __floats2half2_rn(v1.x, v1.y);
            __half2 h3 = __floats2half2_rn(v1.z, v1.w);
            uint4 packed = make_uint4(*(unsigned*)&h0, *(unsigned*)&h1,
                                      *(unsigned*)&h2, *(unsigned*)&h3);
            *(uint4*)(g_W1h + off) = packed;
        }
    } else if (b < NB_INIT + 10) {
        // probe first 2048 u64 words for int32-pair signature
        int base = (b - NB_INIT - 8) * 1024 + threadIdx.x * 4;
        #pragma unroll
        for (int u = 0; u < 4; u++)
            if (ep[base + u] >= (unsigned long long)N_NODES)
                g_is32 = 1;
    } else {
        // W2 convert: 5120 elements over 2 blocks
        int base = (b - NB_INIT - 10) * 2560 + threadIdx.x;
        #pragma unroll
        for (int u = 0; u < 10; u++) {
            int i = base + u * 256;
            if (i < HID_DIM * NCLS) g_W2h[i] = __float2half_rn(W2[i]);
        }
    }
}

// ---------------------------------------------------------------------------
// HMMA gemm1 tile: 64 rows x 128 cols, fp16 in, fp32 accum, fp16 out.
__device__ __forceinline__ void gemm1_tile_mma(const float* __restrict__ X,
                                               int tile) {
    __shared__ __half As[64][72];
    __shared__ __half Bs[64][136];

    const int tid  = threadIdx.x;
    const int wid  = tid >> 5;
    const int lane = tid & 31;
    const int mg   = wid >> 1;
    const int ng   = wid & 1;
    const int block_row = tile * 64;

    float acc[8][4];
    #pragma unroll
    for (int i = 0; i < 8; i++)
        #pragma unroll
        for (int j = 0; j < 4; j++) acc[i][j] = 0.0f;

    const int lr  = lane & 7;
    const int sel = lane >> 3;
    const int aro = (sel & 1) * 8;
    const int aco = (sel >> 1) * 8;

    #pragma unroll
    for (int kc = 0; kc < 2; kc++) {
        const int k0 = kc * 64;

        #pragma unroll
        for (int l = 0; l < 4; l++) {
            int idx = l * 256 + tid;
            int r = idx >> 4;
            int c = (idx & 15) * 4;
            int row = block_row + r;
            float4 v = make_float4(0.f, 0.f, 0.f, 0.f);
            if (row < N_NODES)
                v = *(const float4*)(X + (size_t)row * 128 + k0 + c);
            __half2 h0 = __floats2half2_rn(v.x, v.y);
            __half2 h1 = __floats2half2_rn(v.z, v.w);
            uint2 packed = make_uint2(*(unsigned*)&h0, *(unsigned*)&h1);
            *(uint2*)&As[r][c] = packed;
        }
        #pragma unroll
        for (int l = 0; l < 4; l++) {
            int idx = l * 256 + tid;
            int r = idx >> 4;
            int c = (idx & 15) * 8;
            *(uint4*)&Bs[r][c] = *(const uint4*)(g_W1h + (size_t)(k0 + r) * 128 + c);
        }
        __syncthreads();

        #pragma unroll
        for (int ks = 0; ks < 4; ks++) {
            unsigned a0, a1, a2, a3;
            {
                unsigned ad = smaddr(&As[mg * 16 + aro + lr][ks * 16 + aco]);
                asm volatile(
                    "ldmatrix.sync.aligned.m8n8.x4.shared.b16 {%0,%1,%2,%3}, [%4];"
                    : "=r"(a0), "=r"(a1), "=r"(a2), "=r"(a3) : "r"(ad));
            }
            #pragma unroll
            for (int nt2 = 0; nt2 < 4; nt2++) {
                unsigned b0, b1, b2, b3;
                unsigned bd = smaddr(&Bs[ks * 16 + aro + lr][ng * 64 + nt2 * 16 + aco]);
                asm volatile(
                    "ldmatrix.sync.aligned.m8n8.x4.trans.shared.b16 {%0,%1,%2,%3}, [%4];"
                    : "=r"(b0), "=r"(b1), "=r"(b2), "=r"(b3) : "r"(bd));
                asm volatile(
                    "mma.sync.aligned.m16n8k16.row.col.f32.f16.f16.f32 "
                    "{%0,%1,%2,%3},{%4,%5,%6,%7},{%8,%9},{%0,%1,%2,%3};"
                    : "+f"(acc[nt2*2][0]), "+f"(acc[nt2*2][1]),
                      "+f"(acc[nt2*2][2]), "+f"(acc[nt2*2][3])
                    : "r"(a0), "r"(a1), "r"(a2), "r"(a3), "r"(b0), "r"(b1));
                asm volatile(
                    "mma.sync.aligned.m16n8k16.row.col.f32.f16.f16.f32 "
                    "{%0,%1,%2,%3},{%4,%5,%6,%7},{%8,%9},{%0,%1,%2,%3};"
                    : "+f"(acc[nt2*2+1][0]), "+f"(acc[nt2*2+1][1]),
                      "+f"(acc[nt2*2+1][2]), "+f"(acc[nt2*2+1][3])
                    : "r"(a0), "r"(a1), "r"(a2), "r"(a3), "r"(b2), "r"(b3));
            }
        }
        __syncthreads();
    }

    int g  = lane >> 2;
    int tg = lane & 3;
    #pragma unroll
    for (int nt = 0; nt < 8; nt++) {
        int col = ng * 64 + nt * 8 + tg * 2;
        int row = block_row + mg * 16 + g;
        if (row < N_NODES)
            *(__half2*)(g_H1h + (size_t)row * 128 + col) =
                __floats2half2_rn(acc[nt][0], acc[nt][1]);
        if (row + 8 < N_NODES)
            *(__half2*)(g_H1h + (size_t)(row + 8) * 128 + col) =
                __floats2half2_rn(acc[nt][2], acc[nt][3]);
    }
}

// F1: gemm1 tiles [0, T1_TILES) + degree count over all edges
__global__ void k_f1(const float* __restrict__ X, const void* __restrict__ e) {
    if (blockIdx.x < T1_TILES) {
        gemm1_tile_mma(X, blockIdx.x);
        return;
    }
    int chunk = blockIdx.x - T1_TILES;
    int base = chunk * 1024 + threadIdx.x * 4;
    #pragma unroll
    for (int u = 0; u < 4; u++) {
        int gid = base + u;
        if (gid < NE) {
            int d;
            if (g_is32) d = ((const int*)e)[NE + gid];
            else        d = (int)((const long long*)e)[NE + gid];
            if ((unsigned)d >= N_NODES) d = 0;
            atomicAdd(&g_cnt[d], 1);
        }
    }
}

// F2: gemm1 tiles [T1_TILES, GB1) + CSR scatter over all edges
__global__ void k_f2(const float* __restrict__ X, const void* __restrict__ e) {
    if (blockIdx.x < GB1 - T1_TILES) {
        gemm1_tile_mma(X, T1_TILES + blockIdx.x);
        return;
    }
    int chunk = blockIdx.x - (GB1 - T1_TILES);
    int base = chunk * 1024 + threadIdx.x * 4;
    #pragma unroll
    for (int u = 0; u < 4; u++) {
        int gid = base + u;
        if (gid < NE) {
            int s, d;
            if (g_is32) {
                const int* p = (const int*)e;
                s = p[gid]; d = p[NE + gid];
            } else {
                const long long* p = (const long long*)e;
                s = (int)p[gid]; d = (int)p[NE + gid];
            }
            if ((unsigned)s >= N_NODES) s = 0;
            if ((unsigned)d >= N_NODES) d = 0;
            int pos = g_rowptr[d] + atomicAdd(&g_cur[d], 1);
            g_csr[pos] = s;
        }
    }
}

// --------- scan: per-block sums, then rowptr (embedded sum-scan) -----------
__global__ void k_bsum() {
    __shared__ int sh[SCAN_CHUNK];
    int i = blockIdx.x * SCAN_CHUNK + threadIdx.x;
    sh[threadIdx.x] = (i < N_NODES) ? g_cnt[i] : 0;
    __syncthreads();
    for (int off = SCAN_CHUNK / 2; off > 0; off >>= 1) {
        if (threadIdx.x < off) sh[threadIdx.x] += sh[threadIdx.x + off];
        __syncthreads();
    }
    if (threadIdx.x == 0) g_bsum[blockIdx.x] = sh[0];
}

__global__ void k_rowptr() {
    __shared__ int sh[SCAN_CHUNK];
    __shared__ int bs[128];
    int t = threadIdx.x;

    if (t < 128) bs[t] = (t < NB_SCAN) ? g_bsum[t] : 0;
    __syncthreads();
    #pragma unroll
    for (int off = 1; off < 128; off <<= 1) {
        int v = 0;
        if (t < 128 && t >= off) v = bs[t - off];
        __syncthreads();
        if (t < 128) bs[t] += v;
        __syncthreads();
    }
    int boff = (blockIdx.x == 0) ? 0 : bs[blockIdx.x - 1];

    int i = blockIdx.x * SCAN_CHUNK + t;
    int c = (i < N_NODES) ? g_cnt[i] : 0;
    sh[t] = c;
    __syncthreads();
    for (int off = 1; off < SCAN_CHUNK; off <<= 1) {
        int v = (t >= off) ? sh[t - off] : 0;
        __syncthreads();
        sh[t] += v;
        __syncthreads();
    }
    if (i < N_NODES) {
        int excl = boff + sh[t] - c;
        g_rowptr[i] = excl;
        g_dinv[i] = rsqrtf((float)(c + 1));
        if (i == N_NODES - 1) g_rowptr[N_NODES] = excl + c;
    }
}

// ---------------------------------------------------------------------------
// Fused aggregation + epilogue layer 1: fp16 gather, fp32 accumulate, fp16 out.
__global__ void k_agg1(const float* __restrict__ b1) {
    int node = blockIdx.x * 8 + (threadIdx.x >> 5);
    int lane = threadIdx.x & 31;
    if (node >= N_NODES) return;

    int beg = g_rowptr[node];
    int end = g_rowptr[node + 1];

    float di = g_dinv[node];
    float4 acc;
    {
        uint2 u = *(const uint2*)(g_H1h + (size_t)node * 128 + lane * 4);
        float2 f01 = __half22float2(*(__half2*)&u.x);
        float2 f23 = __half22float2(*(__half2*)&u.y);
        acc.x = f01.x * di; acc.y = f01.y * di;
        acc.z = f23.x * di; acc.w = f23.y * di;
    }

    int j = beg;
    for (; j + 8 <= end; j += 8) {
        int idx[8];
        #pragma unroll
        for (int u = 0; u < 8; u++) idx[u] = g_csr[j + u];
        float w[8];
        #pragma unroll
        for (int u = 0; u < 8; u++) w[u] = g_dinv[idx[u]];
        uint2 h[8];
        #pragma unroll
        for (int u = 0; u < 8; u++)
            h[u] = *(const uint2*)(g_H1h + (size_t)idx[u] * 128 + lane * 4);
        #pragma unroll
        for (int u = 0; u < 8; u++) {
            float2 f01 = __half22float2(*(__half2*)&h[u].x);
            float2 f23 = __half22float2(*(__half2*)&h[u].y);
            acc.x = fmaf(w[u], f01.x, acc.x);
            acc.y = fmaf(w[u], f01.y, acc.y);
            acc.z = fmaf(w[u], f23.x, acc.z);
            acc.w = fmaf(w[u], f23.y, acc.w);
        }
    }
    for (; j < end; j++) {
        int s = g_csr[j];
        float w = g_dinv[s];
        uint2 u = *(const uint2*)(g_H1h + (size_t)s * 128 + lane * 4);
        float2 f01 = __half22float2(*(__half2*)&u.x);
        float2 f23 = __half22float2(*(__half2*)&u.y);
        acc.x = fmaf(w, f01.x, acc.x);
        acc.y = fmaf(w, f01.y, acc.y);
        acc.z = fmaf(w, f23.x, acc.z);
        acc.w = fmaf(w, f23.y, acc.w);
    }

    float4 bb = *(const float4*)(b1 + (size_t)lane * 4);
    float ox = fmaxf(fmaf(acc.x, di, bb.x), 0.0f);
    float oy = fmaxf(fmaf(acc.y, di, bb.y), 0.0f);
    float oz = fmaxf(fmaf(acc.z, di, bb.z), 0.0f);
    float ow = fmaxf(fmaf(acc.w, di, bb.w), 0.0f);
    __half2 h0 = __floats2half2_rn(ox, oy);
    __half2 h1 = __floats2half2_rn(oz, ow);
    uint2 packed = make_uint2(*(unsigned*)&h0, *(unsigned*)&h1);
    *(uint2*)(g_H2h + (size_t)node * 128 + lane * 4) = packed;
}

// ---------------------------------------------------------------------------
// GEMM2 HMMA: g_H3h[N,40] = fp16( dinv * (H2h[N,128] @ W2h[128,40]) )
// M=128/block, N padded 40->48 (3 n16 tiles), K in 2 chunks of 64.
// 8 warps, each m16 x n48.
__global__ void k_gemm2() {
    __shared__ __half As[128][72];   // 18.4 KB (stride 144B: 16B-aligned, conflict-free)
    __shared__ __half Bs[128][56];   // 14.3 KB (stride 112B)

    const int tid  = threadIdx.x;
    const int wid  = tid >> 5;       // m-group 0..7
    const int lane = tid & 31;
    const int row0 = blockIdx.x * 128;

    // Bs: full K=128 rows x 48 cols (zero-padded past 40)
    for (int i = tid; i < 128 * 48; i += 256) {
        int r = i / 48, c = i - r * 48;
        Bs[r][c] = (c < NCLS) ? g_W2h[r * NCLS + c] : __float2half_rn(0.f);
    }

    float acc[6][4];
    #pragma unroll
    for (int i = 0; i < 6; i++)
        #pragma unroll
        for (int j = 0; j < 4; j++) acc[i][j] = 0.0f;

    const int lr  = lane & 7;
    const int sel = lane >> 3;
    const int aro = (sel & 1) * 8;
    const int aco = (sel >> 1) * 8;

    #pragma unroll
    for (int kc = 0; kc < 2; kc++) {
        const int k0 = kc * 64;

        // As: 128 rows x 64 halves from g_H2h (1024 uint4, 4/thread)
        #pragma unroll
        for (int l = 0; l < 4; l++) {
            int idx = l * 256 + tid;
            int r = idx >> 3;
            int c = (idx & 7) * 8;
            int row = row0 + r;
            uint4 v = make_uint4(0u, 0u, 0u, 0u);
            if (row < N_NODES)
                v = *(const uint4*)(g_H2h + (size_t)row * 128 + k0 + c);
            *(uint4*)&As[r][c] = v;
        }
        __syncthreads();

        #pragma unroll
        for (int ks = 0; ks < 4; ks++) {
            unsigned a0, a1, a2, a3;
            {
                unsigned ad = smaddr(&As[wid * 16 + aro + lr][ks * 16 + aco]);
                asm volatile(
                    "ldmatrix.sync.aligned.m8n8.x4.shared.b16 {%0,%1,%2,%3}, [%4];"
                    : "=r"(a0), "=r"(a1), "=r"(a2), "=r"(a3) : "r"(ad));
            }
            #pragma unroll
            for (int nt2 = 0; nt2 < 3; nt2++) {
                unsigned b0, b1, b2, b3;
                unsigned bd = smaddr(&Bs[k0 + ks * 16 + aro + lr][nt2 * 16 + aco]);
                asm volatile(
                    "ldmatrix.sync.aligned.m8n8.x4.trans.shared.b16 {%0,%1,%2,%3}, [%4];"
                    : "=r"(b0), "=r"(b1), "=r"(b2), "=r"(b3) : "r"(bd));
                asm volatile(
                    "mma.sync.aligned.m16n8k16.row.col.f32.f16.f16.f32 "
                    "{%0,%1,%2,%3},{%4,%5,%6,%7},{%8,%9},{%0,%1,%2,%3};"
                    : "+f"(acc[nt2*2][0]), "+f"(acc[nt2*2][1]),
                      "+f"(acc[nt2*2][2]), "+f"(acc[nt2*2][3])
                    : "r"(a0), "r"(a1), "r"(a2), "r"(a3), "r"(b0), "r"(b1));
                asm volatile(
                    "mma.sync.aligned.m16n8k16.row.col.f32.f16.f16.f32 "
                    "{%0,%1,%2,%3},{%4,%5,%6,%7},{%8,%9},{%0,%1,%2,%3};"
                    : "+f"(acc[nt2*2+1][0]), "+f"(acc[nt2*2+1][1]),
                      "+f"(acc[nt2*2+1][2]), "+f"(acc[nt2*2+1][3])
                    : "r"(a0), "r"(a1), "r"(a2), "r"(a3), "r"(b2), "r"(b3));
            }
        }
        __syncthreads();
    }

    int g  = lane >> 2;
    int tg = lane & 3;
    int rowA = row0 + wid * 16 + g;
    int rowB = rowA + 8;
    float diA = (rowA < N_NODES) ? g_dinv[rowA] : 0.f;
    float diB = (rowB < N_NODES) ? g_dinv[rowB] : 0.f;
    #pragma unroll
    for (int nt = 0; nt < 6; nt++) {
        int col = nt * 8 + tg * 2;
        if (col < NCLS) {
            if (rowA < N_NODES)
                *(__half2*)(g_H3h + (size_t)rowA * NCLS + col) =
                    __floats2half2_rn(acc[nt][0] * diA, acc[nt][1] * diA);
            if (rowB < N_NODES)
                *(__half2*)(g_H3h + (size_t)rowB * NCLS + col) =
                    __floats2half2_rn(acc[nt][2] * diB, acc[nt][3] * diB);
        }
    }
}

// ---------------------------------------------------------------------------
// Fused aggregation + epilogue layer 2: fp16 gather, fp32 accumulate.
__global__ void k_agg2(const float* __restrict__ b2, float* __restrict__ out) {
    int node = blockIdx.x * 8 + (threadIdx.x >> 5);
    int lane = threadIdx.x & 31;
    if (node >= N_NODES || lane >= NCLS / 2) return;

    int beg = g_rowptr[node];
    int end = g_rowptr[node + 1];

    float2 acc;
    {
        __half2 h = *((const __half2*)(g_H3h + (size_t)node * NCLS) + lane);
        acc = __half22float2(h);
    }

    int j = beg;
    for (; j + 4 <= end; j += 4) {
        int s0 = g_csr[j], s1 = g_csr[j + 1], s2 = g_csr[j + 2], s3 = g_csr[j + 3];
        __half2 h0 = *((const __half2*)(g_H3h + (size_t)s0 * NCLS) + lane);
        __half2 h1 = *((const __half2*)(g_H3h + (size_t)s1 * NCLS) + lane);
        __half2 h2 = *((const __half2*)(g_H3h + (size_t)s2 * NCLS) + lane);
        __half2 h3 = *((const __half2*)(g_H3h + (size_t)s3 * NCLS) + lane);
        float2 f0 = __half22float2(h0), f1 = __half22float2(h1);
        float2 f2 = __half22float2(h2), f3 = __half22float2(h3);
        acc.x += f0.x + f1.x + f2.x + f3.x;
        acc.y += f0.y + f1.y + f2.y + f3.y;
    }
    for (; j < end; j++) {
        __half2 h = *((const __half2*)(g_H3h + (size_t)g_csr[j] * NCLS) + lane);
        float2 f = __half22float2(h);
        acc.x += f.x; acc.y += f.y;
    }

    float di = g_dinv[node];
    int c = lane * 2;
    out[(size_t)node * NCLS + c]     = fmaf(acc.x, di, b2[c]);
    out[(size_t)node * NCLS + c + 1] = fmaf(acc.y, di, b2[c + 1]);
}

// ---------------------------------------------------------------------------
extern "C" void kernel_launch(void* const* d_in, const int* in_sizes, int n_in,
                              void* d_out, int out_size) {
    const float* x  = (const float*)d_in[0];
    const void*  e  = d_in[1];
    const float* W1 = (const float*)d_in[2];
    const float* b1 = (const float*)d_in[3];
    const float* W2 = (const float*)d_in[4];
    const float* b2 = (const float*)d_in[5];
    float* out = (float*)d_out;

    k_init<<<NB_INIT + 12, 256>>>(W1, W2, (const unsigned long long*)e);
    k_f1<<<T1_TILES + ECHUNKS, 256>>>(x, e);               // gemm1 part A + count
    k_bsum<<<NB_SCAN, SCAN_CHUNK>>>();
    k_rowptr<<<NB_SCAN, SCAN_CHUNK>>>();
    k_f2<<<(GB1 - T1_TILES) + ECHUNKS, 256>>>(x, e);       // gemm1 part B + scatter
    k_agg1<<<(N_NODES + 7) / 8, 256>>>(b1);
    k_gemm2<<<(N_NODES + 127) / 128, 256>>>();
    k_agg2<<<(N_NODES + 7) / 8, 256>>>(b2, out);
}